// round 1
// baseline (speedup 1.0000x reference)
#include <cuda_runtime.h>
#include <math.h>

#define Bq 8
#define Mq 2048
#define Dq 1024
#define Fq 2048
#define Nq 32
#define Pq 4
#define Sq 128   // N*P slots

// ---------------- scratch (device globals; no allocation allowed) ----------
__device__ float g_logits[Bq * Mq * Sq];    // 8 MB   (B,M,S)
__device__ float g_dispatch[Bq * Mq * Sq];  // 8 MB   (B,M,S)
__device__ float g_combine[Bq * Mq * Sq];   // 8 MB   (B,M,S)
__device__ float g_xs[Bq * Sq * Dq];        // 4 MB   (B,S,D)
__device__ float g_h[Bq * Sq * Fq];         // 8 MB   (B,S,F)
__device__ float g_y[Bq * Sq * Dq];         // 4 MB   (B,S,D)

// ---------------- 1) logits[b,m,s] = sum_d x[b,m,d] * phi[d,s] -------------
// grid (M/32, B), block 128 (one thread per slot s), 32-token tile.
__global__ void logits_kernel(const float* __restrict__ x,
                              const float* __restrict__ phi) {
    int b  = blockIdx.y;
    int m0 = blockIdx.x * 32;
    int s  = threadIdx.x;  // 0..127

    __shared__ float xs[32][32];  // [token][k], float4-read rows

    float acc[32];
#pragma unroll
    for (int t = 0; t < 32; t++) acc[t] = 0.f;

    const float* xb = x + ((size_t)b * Mq + m0) * Dq;

    for (int d0 = 0; d0 < Dq; d0 += 32) {
        for (int i = threadIdx.x; i < 32 * 32; i += 128) {
            int t = i >> 5, k = i & 31;
            xs[t][k] = xb[(size_t)t * Dq + d0 + k];
        }
        __syncthreads();

        float ph[32];
#pragma unroll
        for (int k = 0; k < 32; k++) ph[k] = phi[(size_t)(d0 + k) * Sq + s];

#pragma unroll
        for (int t = 0; t < 32; t++) {
            const float4* xr = (const float4*)xs[t];
            float a = 0.f;
#pragma unroll
            for (int k4 = 0; k4 < 8; k4++) {
                float4 v = xr[k4];
                a += v.x * ph[k4 * 4 + 0];
                a += v.y * ph[k4 * 4 + 1];
                a += v.z * ph[k4 * 4 + 2];
                a += v.w * ph[k4 * 4 + 3];
            }
            acc[t] += a;
        }
        __syncthreads();
    }

    float* lb = g_logits + ((size_t)b * Mq + m0) * Sq + s;
#pragma unroll
    for (int t = 0; t < 32; t++) lb[(size_t)t * Sq] = acc[t];
}

// ---------------- 2a) combine = softmax over S per (b,m) -------------------
// one warp per token; 8 warps per block.
__global__ void combine_kernel() {
    int token = blockIdx.x * 8 + (threadIdx.x >> 5);
    int lane  = threadIdx.x & 31;
    const float* lp = g_logits + (size_t)token * Sq;

    float v[4];
    float mx = -1e30f;
#pragma unroll
    for (int j = 0; j < 4; j++) {
        v[j] = lp[lane + j * 32];
        mx = fmaxf(mx, v[j]);
    }
#pragma unroll
    for (int off = 16; off > 0; off >>= 1)
        mx = fmaxf(mx, __shfl_xor_sync(0xffffffffu, mx, off));

    float e[4];
    float sum = 0.f;
#pragma unroll
    for (int j = 0; j < 4; j++) {
        e[j] = expf(v[j] - mx);
        sum += e[j];
    }
#pragma unroll
    for (int off = 16; off > 0; off >>= 1)
        sum += __shfl_xor_sync(0xffffffffu, sum, off);

    float inv = 1.f / sum;
    float* cp = g_combine + (size_t)token * Sq;
#pragma unroll
    for (int j = 0; j < 4; j++) cp[lane + j * 32] = e[j] * inv;
}

// ---------------- 2b) dispatch = softmax over M per (b,s) ------------------
// grid (S/32, B), block (32,32). tx indexes s (coalesced), ty strides m.
__global__ void dispatch_kernel() {
    int b  = blockIdx.y;
    int s  = blockIdx.x * 32 + threadIdx.x;
    int tx = threadIdx.x, ty = threadIdx.y;

    __shared__ float red[32][33];

    const float* lp = g_logits + (size_t)b * Mq * Sq + s;

    float mx = -1e30f;
    for (int m = ty; m < Mq; m += 32) mx = fmaxf(mx, lp[(size_t)m * Sq]);
    red[ty][tx] = mx;
    __syncthreads();
    for (int off = 16; off > 0; off >>= 1) {
        if (ty < off) red[ty][tx] = fmaxf(red[ty][tx], red[ty + off][tx]);
        __syncthreads();
    }
    mx = red[0][tx];
    __syncthreads();

    float sum = 0.f;
    for (int m = ty; m < Mq; m += 32) sum += expf(lp[(size_t)m * Sq] - mx);
    red[ty][tx] = sum;
    __syncthreads();
    for (int off = 16; off > 0; off >>= 1) {
        if (ty < off) red[ty][tx] += red[ty + off][tx];
        __syncthreads();
    }
    float inv = 1.f / red[0][tx];

    float* dp = g_dispatch + (size_t)b * Mq * Sq + s;
    for (int m = ty; m < Mq; m += 32)
        dp[(size_t)m * Sq] = expf(lp[(size_t)m * Sq] - mx) * inv;
}

// ---------------- 3) xs[b,s,d] = sum_m dispatch[b,m,s] * x[b,m,d] ----------
// grid (D/64, S/32, B), block 256. Tile 32s x 64d, K=M chunk 32.
__global__ void xs_kernel(const float* __restrict__ x) {
    int b  = blockIdx.z;
    int s0 = blockIdx.y * 32;
    int d0 = blockIdx.x * 64;

    __shared__ float ds[32][33];  // [m][s]
    __shared__ float xt[32][64];  // [m][d]

    int tid = threadIdx.x;
    int cx = tid & 15;   // 4 d-cols each
    int sy = tid >> 4;   // 16 groups, 2 s-rows each

    float acc[2][4] = {};

    for (int m0 = 0; m0 < Mq; m0 += 32) {
        for (int i = tid; i < 32 * 32; i += 256) {
            int mm = i >> 5, ss = i & 31;
            ds[mm][ss] = g_dispatch[((size_t)b * Mq + m0 + mm) * Sq + s0 + ss];
        }
        for (int i = tid; i < 32 * 64; i += 256) {
            int mm = i >> 6, dd = i & 63;
            xt[mm][dd] = x[((size_t)b * Mq + m0 + mm) * Dq + d0 + dd];
        }
        __syncthreads();
#pragma unroll
        for (int kk = 0; kk < 32; kk++) {
            float dv0 = ds[kk][sy * 2 + 0];
            float dv1 = ds[kk][sy * 2 + 1];
            float4 xv = *(const float4*)&xt[kk][cx * 4];
            acc[0][0] += dv0 * xv.x; acc[0][1] += dv0 * xv.y;
            acc[0][2] += dv0 * xv.z; acc[0][3] += dv0 * xv.w;
            acc[1][0] += dv1 * xv.x; acc[1][1] += dv1 * xv.y;
            acc[1][2] += dv1 * xv.z; acc[1][3] += dv1 * xv.w;
        }
        __syncthreads();
    }

#pragma unroll
    for (int j = 0; j < 2; j++) {
        float4 v = make_float4(acc[j][0], acc[j][1], acc[j][2], acc[j][3]);
        *(float4*)&g_xs[((size_t)b * Sq + s0 + sy * 2 + j) * Dq + d0 + cx * 4] = v;
    }
}

// ---------------- 4a) h = relu(xs @ w1 + b1)^2 per expert -------------------
// grid (F/128, N), block 256. Rows = 32 (b,p) pairs, cols = 128 f, K = D.
__global__ void ffn1_kernel(const float* __restrict__ w1,
                            const float* __restrict__ b1) {
    int n  = blockIdx.y;
    int f0 = blockIdx.x * 128;

    __shared__ float A[32][33];   // [row][k]
    __shared__ float W[32][128];  // [k][f]

    int tid = threadIdx.x;
    int cx = tid & 15;  // 8 f-cols each
    int ry = tid >> 4;  // rows {ry, ry+16}

    float acc[2][8] = {};

    for (int k0 = 0; k0 < Dq; k0 += 32) {
        for (int i = tid; i < 32 * 32; i += 256) {
            int r = i >> 5, k = i & 31;
            int bb = r >> 2, pp = r & 3;
            A[r][k] = g_xs[((size_t)bb * Sq + n * 4 + pp) * Dq + k0 + k];
        }
        for (int i = tid; i < 32 * 128; i += 256) {
            int k = i >> 7, f = i & 127;
            W[k][f] = w1[((size_t)n * Dq + k0 + k) * Fq + f0 + f];
        }
        __syncthreads();
#pragma unroll
        for (int kk = 0; kk < 32; kk++) {
            float a0 = A[ry][kk];
            float a1 = A[ry + 16][kk];
            float4 w0 = *(const float4*)&W[kk][cx * 8];
            float4 w1v = *(const float4*)&W[kk][cx * 8 + 4];
            acc[0][0] += a0 * w0.x;  acc[0][1] += a0 * w0.y;
            acc[0][2] += a0 * w0.z;  acc[0][3] += a0 * w0.w;
            acc[0][4] += a0 * w1v.x; acc[0][5] += a0 * w1v.y;
            acc[0][6] += a0 * w1v.z; acc[0][7] += a0 * w1v.w;
            acc[1][0] += a1 * w0.x;  acc[1][1] += a1 * w0.y;
            acc[1][2] += a1 * w0.z;  acc[1][3] += a1 * w0.w;
            acc[1][4] += a1 * w1v.x; acc[1][5] += a1 * w1v.y;
            acc[1][6] += a1 * w1v.z; acc[1][7] += a1 * w1v.w;
        }
        __syncthreads();
    }

#pragma unroll
    for (int j = 0; j < 2; j++) {
        int r = ry + j * 16;
        int bb = r >> 2, pp = r & 3;
        int s = n * 4 + pp;
        float o[8];
#pragma unroll
        for (int i = 0; i < 8; i++) {
            float hv = acc[j][i] + b1[(size_t)n * Fq + f0 + cx * 8 + i];
            hv = fmaxf(hv, 0.f);
            o[i] = hv * hv;
        }
        float* hp = &g_h[((size_t)bb * Sq + s) * Fq + f0 + cx * 8];
        *(float4*)hp = make_float4(o[0], o[1], o[2], o[3]);
        *(float4*)(hp + 4) = make_float4(o[4], o[5], o[6], o[7]);
    }
}

// ---------------- 4b) y = h @ w2 + b2 per expert ----------------------------
// grid (D/128, N), block 256. Rows = 32 (b,p), cols = 128 d, K = F.
__global__ void ffn2_kernel(const float* __restrict__ w2,
                            const float* __restrict__ b2) {
    int n  = blockIdx.y;
    int d0 = blockIdx.x * 128;

    __shared__ float A[32][33];
    __shared__ float W[32][128];

    int tid = threadIdx.x;
    int cx = tid & 15;
    int ry = tid >> 4;

    float acc[2][8] = {};

    for (int k0 = 0; k0 < Fq; k0 += 32) {
        for (int i = tid; i < 32 * 32; i += 256) {
            int r = i >> 5, k = i & 31;
            int bb = r >> 2, pp = r & 3;
            A[r][k] = g_h[((size_t)bb * Sq + n * 4 + pp) * Fq + k0 + k];
        }
        for (int i = tid; i < 32 * 128; i += 256) {
            int k = i >> 7, d = i & 127;
            W[k][d] = w2[((size_t)n * Fq + k0 + k) * Dq + d0 + d];
        }
        __syncthreads();
#pragma unroll
        for (int kk = 0; kk < 32; kk++) {
            float a0 = A[ry][kk];
            float a1 = A[ry + 16][kk];
            float4 w0 = *(const float4*)&W[kk][cx * 8];
            float4 w1v = *(const float4*)&W[kk][cx * 8 + 4];
            acc[0][0] += a0 * w0.x;  acc[0][1] += a0 * w0.y;
            acc[0][2] += a0 * w0.z;  acc[0][3] += a0 * w0.w;
            acc[0][4] += a0 * w1v.x; acc[0][5] += a0 * w1v.y;
            acc[0][6] += a0 * w1v.z; acc[0][7] += a0 * w1v.w;
            acc[1][0] += a1 * w0.x;  acc[1][1] += a1 * w0.y;
            acc[1][2] += a1 * w0.z;  acc[1][3] += a1 * w0.w;
            acc[1][4] += a1 * w1v.x; acc[1][5] += a1 * w1v.y;
            acc[1][6] += a1 * w1v.z; acc[1][7] += a1 * w1v.w;
        }
        __syncthreads();
    }

#pragma unroll
    for (int j = 0; j < 2; j++) {
        int r = ry + j * 16;
        int bb = r >> 2, pp = r & 3;
        int s = n * 4 + pp;
        float o[8];
#pragma unroll
        for (int i = 0; i < 8; i++)
            o[i] = acc[j][i] + b2[(size_t)n * Dq + d0 + cx * 8 + i];
        float* yp = &g_y[((size_t)bb * Sq + s) * Dq + d0 + cx * 8];
        *(float4*)yp = make_float4(o[0], o[1], o[2], o[3]);
        *(float4*)(yp + 4) = make_float4(o[4], o[5], o[6], o[7]);
    }
}

// ---------------- 5) out[b,m,d] = sum_s combine[b,m,s] * y[b,s,d] ----------
// grid (D/64, M/64, B), block 256. Tile 64m x 64d, K=S in chunks of 32.
__global__ void out_kernel(float* __restrict__ out) {
    int b  = blockIdx.z;
    int m0 = blockIdx.y * 64;
    int d0 = blockIdx.x * 64;

    __shared__ float C[64][33];  // [m][s]
    __shared__ float Y[32][64];  // [s][d]

    int tid = threadIdx.x;
    int cx = tid & 15;  // 4 d each
    int ry = tid >> 4;  // rows {ry, ry+16, ry+32, ry+48}

    float acc[4][4] = {};

    for (int s0 = 0; s0 < Sq; s0 += 32) {
        for (int i = tid; i < 64 * 32; i += 256) {
            int mm = i >> 5, ss = i & 31;
            C[mm][ss] = g_combine[((size_t)b * Mq + m0 + mm) * Sq + s0 + ss];
        }
        for (int i = tid; i < 32 * 64; i += 256) {
            int ss = i >> 6, dd = i & 63;
            Y[ss][dd] = g_y[((size_t)b * Sq + s0 + ss) * Dq + d0 + dd];
        }
        __syncthreads();
#pragma unroll
        for (int kk = 0; kk < 32; kk++) {
            float4 yv = *(const float4*)&Y[kk][cx * 4];
#pragma unroll
            for (int j = 0; j < 4; j++) {
                float cv = C[ry + j * 16][kk];
                acc[j][0] += cv * yv.x; acc[j][1] += cv * yv.y;
                acc[j][2] += cv * yv.z; acc[j][3] += cv * yv.w;
            }
        }
        __syncthreads();
    }

#pragma unroll
    for (int j = 0; j < 4; j++) {
        float4 v = make_float4(acc[j][0], acc[j][1], acc[j][2], acc[j][3]);
        *(float4*)&out[((size_t)b * Mq + m0 + ry + j * 16) * Dq + d0 + cx * 4] = v;
    }
}

// ---------------------------------------------------------------------------
extern "C" void kernel_launch(void* const* d_in, const int* in_sizes, int n_in,
                              void* d_out, int out_size) {
    const float* x   = (const float*)d_in[0];
    const float* phi = (const float*)d_in[1];
    const float* w1  = (const float*)d_in[2];
    const float* b1  = (const float*)d_in[3];
    const float* w2  = (const float*)d_in[4];
    const float* b2  = (const float*)d_in[5];
    float* out = (float*)d_out;

    logits_kernel<<<dim3(Mq / 32, Bq), 128>>>(x, phi);
    combine_kernel<<<(Bq * Mq) / 8, 256>>>();
    dispatch_kernel<<<dim3(Sq / 32, Bq), dim3(32, 32)>>>();
    xs_kernel<<<dim3(Dq / 64, Sq / 32, Bq), 256>>>(x);
    ffn1_kernel<<<dim3(Fq / 128, Nq), 256>>>(w1, b1);
    ffn2_kernel<<<dim3(Dq / 128, Nq), 256>>>(w2, b2);
    out_kernel<<<dim3(Dq / 64, Mq / 64, Bq), 256>>>(out);
}

// round 2
// speedup vs baseline: 3.8187x; 3.8187x over previous
#include <cuda_runtime.h>
#include <math.h>
#include <stdint.h>

#define Bq 8
#define Mq 2048
#define Dq 1024
#define Fq 2048
#define Nq 32
#define Pq 4
#define Sq 128   // N*P slots

// ---------------- scratch (device globals; no allocation allowed) ----------
__device__ float g_logits[Bq * Mq * Sq];    // 8 MB   (B,M,S)
__device__ float g_dispatch[Bq * Mq * Sq];  // 8 MB   (B,M,S)
__device__ float g_combine[Bq * Mq * Sq];   // 8 MB   (B,M,S)
__device__ float g_xs[Bq * Sq * Dq];        // 4 MB   (B,S,D)
__device__ float g_h[Bq * Sq * Fq];         // 8 MB   (B,S,F)
__device__ float g_y[Bq * Sq * Dq];         // 4 MB   (B,S,D)

// float -> tf32 (round-to-nearest) kept in a 32-bit register
__device__ __forceinline__ uint32_t f2tf32(float f) {
    uint32_t r;
    asm("cvt.rna.tf32.f32 %0, %1;" : "=r"(r) : "f"(f));
    return r;
}

// One KC=16 chunk of warp-tile MMA work.
// As: [k][m] with row stride AST (uint32 elems), Bs: [k][n] stride BST.
// acc[MT][NT][4] accumulators, m16n8k8 tf32 mma.
template <int MT, int NT, int AST, int BST>
__device__ __forceinline__ void mma_chunk(const uint32_t* __restrict__ As,
                                          const uint32_t* __restrict__ Bs,
                                          int mbase, int nbase,
                                          float (*acc)[NT][4]) {
    int lane = threadIdx.x & 31;
    int g = lane >> 2, tg = lane & 3;
#pragma unroll
    for (int ks = 0; ks < 2; ks++) {
        uint32_t a[MT][4], b[NT][2];
#pragma unroll
        for (int i = 0; i < MT; i++) {
            const uint32_t* p = As + (ks * 8 + tg) * AST + mbase + i * 16 + g;
            a[i][0] = p[0];
            a[i][1] = p[8];
            a[i][2] = p[4 * AST];
            a[i][3] = p[4 * AST + 8];
        }
#pragma unroll
        for (int j = 0; j < NT; j++) {
            const uint32_t* p = Bs + (ks * 8 + tg) * BST + nbase + j * 8 + g;
            b[j][0] = p[0];
            b[j][1] = p[4 * BST];
        }
#pragma unroll
        for (int i = 0; i < MT; i++)
#pragma unroll
            for (int j = 0; j < NT; j++)
                asm volatile(
                    "mma.sync.aligned.m16n8k8.row.col.f32.tf32.tf32.f32 "
                    "{%0,%1,%2,%3},{%4,%5,%6,%7},{%8,%9},{%0,%1,%2,%3};\n"
                    : "+f"(acc[i][j][0]), "+f"(acc[i][j][1]),
                      "+f"(acc[i][j][2]), "+f"(acc[i][j][3])
                    : "r"(a[i][0]), "r"(a[i][1]), "r"(a[i][2]), "r"(a[i][3]),
                      "r"(b[j][0]), "r"(b[j][1]));
    }
}

// ============ 1) logits[b,m,s] = sum_d x[b,m,d] * phi[d,s] ==================
// BM=128(m) BN=128(s) K=1024. warps 2x4 -> WM=64 WN=32, MT=4 NT=4.
__global__ void __launch_bounds__(256) logits_mma(const float* __restrict__ x,
                                                  const float* __restrict__ phi) {
    const int b = blockIdx.y;
    const int m0 = blockIdx.x * 128;
    __shared__ uint32_t As[16][136];
    __shared__ uint32_t Bs[16][136];

    int tid = threadIdx.x, warp = tid >> 5, lane = tid & 31;
    int mbase = (warp >> 2) * 64, nbase = (warp & 3) * 32;
    float acc[4][4][4] = {};

    const float* xb = x + ((size_t)b * Mq + m0) * Dq;
    float4 ra[2], rb[2];

    const int NC = Dq / 16;
#pragma unroll 1
    for (int c = 0; c <= NC; c++) {
        if (c < NC) {
            int k0 = c * 16;
#pragma unroll
            for (int i = 0; i < 2; i++) {
                int f = tid + i * 256;
                ra[i] = *(const float4*)&xb[(size_t)(f >> 2) * Dq + k0 + (f & 3) * 4];
                rb[i] = *(const float4*)&phi[(size_t)(k0 + (f >> 5)) * Sq + (f & 31) * 4];
            }
        }
        if (c > 0)
            mma_chunk<4, 4, 136, 136>(&As[0][0], &Bs[0][0], mbase, nbase, acc);
        __syncthreads();
        if (c < NC) {
#pragma unroll
            for (int i = 0; i < 2; i++) {
                int f = tid + i * 256;
                int r = f >> 2, cc = f & 3;
                As[cc * 4 + 0][r] = f2tf32(ra[i].x);
                As[cc * 4 + 1][r] = f2tf32(ra[i].y);
                As[cc * 4 + 2][r] = f2tf32(ra[i].z);
                As[cc * 4 + 3][r] = f2tf32(ra[i].w);
                uint4 v = make_uint4(f2tf32(rb[i].x), f2tf32(rb[i].y),
                                     f2tf32(rb[i].z), f2tf32(rb[i].w));
                *(uint4*)&Bs[f >> 5][(f & 31) * 4] = v;
            }
            __syncthreads();
        }
    }

    int g = lane >> 2, tg = lane & 3;
    float* lb = g_logits + ((size_t)b * Mq + m0) * Sq;
#pragma unroll
    for (int i = 0; i < 4; i++)
#pragma unroll
        for (int j = 0; j < 4; j++) {
            int row = mbase + i * 16 + g, col = nbase + j * 8 + tg * 2;
            *(float2*)&lb[(size_t)row * Sq + col] = make_float2(acc[i][j][0], acc[i][j][1]);
            *(float2*)&lb[(size_t)(row + 8) * Sq + col] = make_float2(acc[i][j][2], acc[i][j][3]);
        }
}

// ============ 2a) combine = softmax over S per (b,m) =======================
__global__ void combine_kernel() {
    int token = blockIdx.x * 8 + (threadIdx.x >> 5);
    int lane = threadIdx.x & 31;
    const float* lp = g_logits + (size_t)token * Sq;

    float v[4];
    float mx = -1e30f;
#pragma unroll
    for (int j = 0; j < 4; j++) {
        v[j] = lp[lane + j * 32];
        mx = fmaxf(mx, v[j]);
    }
#pragma unroll
    for (int off = 16; off > 0; off >>= 1)
        mx = fmaxf(mx, __shfl_xor_sync(0xffffffffu, mx, off));

    float e[4];
    float sum = 0.f;
#pragma unroll
    for (int j = 0; j < 4; j++) {
        e[j] = expf(v[j] - mx);
        sum += e[j];
    }
#pragma unroll
    for (int off = 16; off > 0; off >>= 1)
        sum += __shfl_xor_sync(0xffffffffu, sum, off);

    float inv = 1.f / sum;
    float* cp = g_combine + (size_t)token * Sq;
#pragma unroll
    for (int j = 0; j < 4; j++) cp[lane + j * 32] = e[j] * inv;
}

// ============ 2b) dispatch = softmax over M per (b,s) ======================
__global__ void dispatch_kernel() {
    int b = blockIdx.y;
    int s = blockIdx.x * 32 + threadIdx.x;
    int tx = threadIdx.x, ty = threadIdx.y;

    __shared__ float red[32][33];

    const float* lp = g_logits + (size_t)b * Mq * Sq + s;

    float mx = -1e30f;
    for (int m = ty; m < Mq; m += 32) mx = fmaxf(mx, lp[(size_t)m * Sq]);
    red[ty][tx] = mx;
    __syncthreads();
    for (int off = 16; off > 0; off >>= 1) {
        if (ty < off) red[ty][tx] = fmaxf(red[ty][tx], red[ty + off][tx]);
        __syncthreads();
    }
    mx = red[0][tx];
    __syncthreads();

    float sum = 0.f;
    for (int m = ty; m < Mq; m += 32) sum += expf(lp[(size_t)m * Sq] - mx);
    red[ty][tx] = sum;
    __syncthreads();
    for (int off = 16; off > 0; off >>= 1) {
        if (ty < off) red[ty][tx] += red[ty + off][tx];
        __syncthreads();
    }
    float inv = 1.f / red[0][tx];

    float* dp = g_dispatch + (size_t)b * Mq * Sq + s;
    for (int m = ty; m < Mq; m += 32)
        dp[(size_t)m * Sq] = expf(lp[(size_t)m * Sq] - mx) * inv;
}

// ============ 3) xs[b,s,d] = sum_m dispatch[b,m,s] * x[b,m,d] ==============
// BM=64(s) BN=128(d) K=2048. warps 2x4 -> WM=32 WN=32, MT=2 NT=4.
__global__ void __launch_bounds__(256) xs_mma(const float* __restrict__ x) {
    const int b = blockIdx.z;
    const int s0 = blockIdx.y * 64;
    const int d0 = blockIdx.x * 128;
    __shared__ uint32_t As[16][72];
    __shared__ uint32_t Bs[16][136];

    int tid = threadIdx.x, warp = tid >> 5, lane = tid & 31;
    int mbase = (warp >> 2) * 32, nbase = (warp & 3) * 32;
    float acc[2][4][4] = {};

    float4 ra, rb[2];
    const int NC = Mq / 16;
#pragma unroll 1
    for (int c = 0; c <= NC; c++) {
        if (c < NC) {
            int k0 = c * 16;
            ra = *(const float4*)&g_dispatch[((size_t)b * Mq + k0 + (tid >> 4)) * Sq +
                                             s0 + (tid & 15) * 4];
#pragma unroll
            for (int i = 0; i < 2; i++) {
                int f = tid + i * 256;
                rb[i] = *(const float4*)&x[((size_t)b * Mq + k0 + (f >> 5)) * Dq +
                                           d0 + (f & 31) * 4];
            }
        }
        if (c > 0)
            mma_chunk<2, 4, 72, 136>(&As[0][0], &Bs[0][0], mbase, nbase, acc);
        __syncthreads();
        if (c < NC) {
            uint4 va = make_uint4(f2tf32(ra.x), f2tf32(ra.y), f2tf32(ra.z), f2tf32(ra.w));
            *(uint4*)&As[tid >> 4][(tid & 15) * 4] = va;
#pragma unroll
            for (int i = 0; i < 2; i++) {
                int f = tid + i * 256;
                uint4 v = make_uint4(f2tf32(rb[i].x), f2tf32(rb[i].y),
                                     f2tf32(rb[i].z), f2tf32(rb[i].w));
                *(uint4*)&Bs[f >> 5][(f & 31) * 4] = v;
            }
            __syncthreads();
        }
    }

    int g = lane >> 2, tg = lane & 3;
#pragma unroll
    for (int i = 0; i < 2; i++)
#pragma unroll
        for (int j = 0; j < 4; j++) {
            int row = s0 + mbase + i * 16 + g, col = d0 + nbase + j * 8 + tg * 2;
            *(float2*)&g_xs[((size_t)b * Sq + row) * Dq + col] =
                make_float2(acc[i][j][0], acc[i][j][1]);
            *(float2*)&g_xs[((size_t)b * Sq + row + 8) * Dq + col] =
                make_float2(acc[i][j][2], acc[i][j][3]);
        }
}

// ============ 4a) h = relu(xs @ w1 + b1)^2 per expert ======================
// BM=32(rows=(b,p)) BN=128(f) K=1024. warps 1x8 -> WN=16, MT=2 NT=2.
__global__ void __launch_bounds__(256) ffn1_mma(const float* __restrict__ w1,
                                                const float* __restrict__ b1) {
    const int n = blockIdx.y;
    const int f0 = blockIdx.x * 128;
    __shared__ uint32_t As[16][40];
    __shared__ uint32_t Bs[16][136];

    int tid = threadIdx.x, warp = tid >> 5, lane = tid & 31;
    int nbase = warp * 16;
    float acc[2][2][4] = {};

    float4 ra, rb[2];
    const int NC = Dq / 16;
#pragma unroll 1
    for (int c = 0; c <= NC; c++) {
        if (c < NC) {
            int k0 = c * 16;
            if (tid < 128) {
                int r = tid >> 2;
                ra = *(const float4*)&g_xs[(((size_t)(r >> 2)) * Sq + n * 4 + (r & 3)) * Dq +
                                           k0 + (tid & 3) * 4];
            }
#pragma unroll
            for (int i = 0; i < 2; i++) {
                int f = tid + i * 256;
                rb[i] = *(const float4*)&w1[((size_t)n * Dq + k0 + (f >> 5)) * Fq +
                                            f0 + (f & 31) * 4];
            }
        }
        if (c > 0)
            mma_chunk<2, 2, 40, 136>(&As[0][0], &Bs[0][0], 0, nbase, acc);
        __syncthreads();
        if (c < NC) {
            if (tid < 128) {
                int r = tid >> 2, cc = tid & 3;
                As[cc * 4 + 0][r] = f2tf32(ra.x);
                As[cc * 4 + 1][r] = f2tf32(ra.y);
                As[cc * 4 + 2][r] = f2tf32(ra.z);
                As[cc * 4 + 3][r] = f2tf32(ra.w);
            }
#pragma unroll
            for (int i = 0; i < 2; i++) {
                int f = tid + i * 256;
                uint4 v = make_uint4(f2tf32(rb[i].x), f2tf32(rb[i].y),
                                     f2tf32(rb[i].z), f2tf32(rb[i].w));
                *(uint4*)&Bs[f >> 5][(f & 31) * 4] = v;
            }
            __syncthreads();
        }
    }

    int g = lane >> 2, tg = lane & 3;
#pragma unroll
    for (int i = 0; i < 2; i++)
#pragma unroll
        for (int j = 0; j < 2; j++) {
            int row = i * 16 + g;
            int col = nbase + j * 8 + tg * 2;
#pragma unroll
            for (int half = 0; half < 2; half++) {
                int rr = row + half * 8;
                float h0 = acc[i][j][half * 2 + 0] + b1[(size_t)n * Fq + f0 + col];
                float h1 = acc[i][j][half * 2 + 1] + b1[(size_t)n * Fq + f0 + col + 1];
                h0 = fmaxf(h0, 0.f); h1 = fmaxf(h1, 0.f);
                float* hp = &g_h[(((size_t)(rr >> 2)) * Sq + n * 4 + (rr & 3)) * Fq + f0 + col];
                *(float2*)hp = make_float2(h0 * h0, h1 * h1);
            }
        }
}

// ============ 4b) y = h @ w2 + b2 per expert ===============================
// BM=32 BN=64(d) K=2048. warps 1x8 -> WN=8, MT=2 NT=1.
__global__ void __launch_bounds__(256) ffn2_mma(const float* __restrict__ w2,
                                                const float* __restrict__ b2) {
    const int n = blockIdx.y;
    const int d0 = blockIdx.x * 64;
    __shared__ uint32_t As[16][40];
    __shared__ uint32_t Bs[16][72];

    int tid = threadIdx.x, warp = tid >> 5, lane = tid & 31;
    int nbase = warp * 8;
    float acc[2][1][4] = {};

    float4 ra, rb;
    const int NC = Fq / 16;
#pragma unroll 1
    for (int c = 0; c <= NC; c++) {
        if (c < NC) {
            int k0 = c * 16;
            if (tid < 128) {
                int r = tid >> 2;
                ra = *(const float4*)&g_h[(((size_t)(r >> 2)) * Sq + n * 4 + (r & 3)) * Fq +
                                          k0 + (tid & 3) * 4];
            }
            rb = *(const float4*)&w2[((size_t)n * Fq + k0 + (tid >> 4)) * Dq +
                                     d0 + (tid & 15) * 4];
        }
        if (c > 0)
            mma_chunk<2, 1, 40, 72>(&As[0][0], &Bs[0][0], 0, nbase, acc);
        __syncthreads();
        if (c < NC) {
            if (tid < 128) {
                int r = tid >> 2, cc = tid & 3;
                As[cc * 4 + 0][r] = f2tf32(ra.x);
                As[cc * 4 + 1][r] = f2tf32(ra.y);
                As[cc * 4 + 2][r] = f2tf32(ra.z);
                As[cc * 4 + 3][r] = f2tf32(ra.w);
            }
            uint4 v = make_uint4(f2tf32(rb.x), f2tf32(rb.y), f2tf32(rb.z), f2tf32(rb.w));
            *(uint4*)&Bs[tid >> 4][(tid & 15) * 4] = v;
            __syncthreads();
        }
    }

    int g = lane >> 2, tg = lane & 3;
#pragma unroll
    for (int i = 0; i < 2; i++) {
        int row = i * 16 + g;
        int col = d0 + nbase + tg * 2;
#pragma unroll
        for (int half = 0; half < 2; half++) {
            int rr = row + half * 8;
            float y0 = acc[i][0][half * 2 + 0] + b2[(size_t)n * Dq + col];
            float y1 = acc[i][0][half * 2 + 1] + b2[(size_t)n * Dq + col + 1];
            float* yp = &g_y[(((size_t)(rr >> 2)) * Sq + n * 4 + (rr & 3)) * Dq + col];
            *(float2*)yp = make_float2(y0, y1);
        }
    }
}

// ============ 5) out[b,m,d] = sum_s combine[b,m,s] * y[b,s,d] ==============
// BM=128(m) BN=128(d) K=128. warps 2x4 -> MT=4 NT=4.
__global__ void __launch_bounds__(256) out_mma(float* __restrict__ out) {
    const int b = blockIdx.z;
    const int m0 = blockIdx.y * 128;
    const int d0 = blockIdx.x * 128;
    __shared__ uint32_t As[16][136];
    __shared__ uint32_t Bs[16][136];

    int tid = threadIdx.x, warp = tid >> 5, lane = tid & 31;
    int mbase = (warp >> 2) * 64, nbase = (warp & 3) * 32;
    float acc[4][4][4] = {};

    const float* cb = g_combine + ((size_t)b * Mq + m0) * Sq;
    float4 ra[2], rb[2];

    const int NC = Sq / 16;  // 8
#pragma unroll 1
    for (int c = 0; c <= NC; c++) {
        if (c < NC) {
            int k0 = c * 16;
#pragma unroll
            for (int i = 0; i < 2; i++) {
                int f = tid + i * 256;
                ra[i] = *(const float4*)&cb[(size_t)(f >> 2) * Sq + k0 + (f & 3) * 4];
                rb[i] = *(const float4*)&g_y[((size_t)b * Sq + k0 + (f >> 5)) * Dq +
                                             d0 + (f & 31) * 4];
            }
        }
        if (c > 0)
            mma_chunk<4, 4, 136, 136>(&As[0][0], &Bs[0][0], mbase, nbase, acc);
        __syncthreads();
        if (c < NC) {
#pragma unroll
            for (int i = 0; i < 2; i++) {
                int f = tid + i * 256;
                int r = f >> 2, cc = f & 3;
                As[cc * 4 + 0][r] = f2tf32(ra[i].x);
                As[cc * 4 + 1][r] = f2tf32(ra[i].y);
                As[cc * 4 + 2][r] = f2tf32(ra[i].z);
                As[cc * 4 + 3][r] = f2tf32(ra[i].w);
                uint4 v = make_uint4(f2tf32(rb[i].x), f2tf32(rb[i].y),
                                     f2tf32(rb[i].z), f2tf32(rb[i].w));
                *(uint4*)&Bs[f >> 5][(f & 31) * 4] = v;
            }
            __syncthreads();
        }
    }

    int g = lane >> 2, tg = lane & 3;
    float* ob = out + ((size_t)b * Mq + m0) * Dq + d0;
#pragma unroll
    for (int i = 0; i < 4; i++)
#pragma unroll
        for (int j = 0; j < 4; j++) {
            int row = mbase + i * 16 + g, col = nbase + j * 8 + tg * 2;
            *(float2*)&ob[(size_t)row * Dq + col] = make_float2(acc[i][j][0], acc[i][j][1]);
            *(float2*)&ob[(size_t)(row + 8) * Dq + col] = make_float2(acc[i][j][2], acc[i][j][3]);
        }
}

// ---------------------------------------------------------------------------
extern "C" void kernel_launch(void* const* d_in, const int* in_sizes, int n_in,
                              void* d_out, int out_size) {
    const float* x   = (const float*)d_in[0];
    const float* phi = (const float*)d_in[1];
    const float* w1  = (const float*)d_in[2];
    const float* b1  = (const float*)d_in[3];
    const float* w2  = (const float*)d_in[4];
    const float* b2  = (const float*)d_in[5];
    float* out = (float*)d_out;

    logits_mma<<<dim3(Mq / 128, Bq), 256>>>(x, phi);
    combine_kernel<<<(Bq * Mq) / 8, 256>>>();
    dispatch_kernel<<<dim3(Sq / 32, Bq), dim3(32, 32)>>>();
    xs_mma<<<dim3(Dq / 128, Sq / 64, Bq), 256>>>(x);
    ffn1_mma<<<dim3(Fq / 128, Nq), 256>>>(w1, b1);
    ffn2_mma<<<dim3(Dq / 64, Nq), 256>>>(w2, b2);
    out_mma<<<dim3(Dq / 128, Mq / 128, Bq), 256>>>(out);
}

// round 3
// speedup vs baseline: 4.1484x; 1.0863x over previous
#include <cuda_runtime.h>
#include <math.h>
#include <stdint.h>

#define Bq 8
#define Mq 2048
#define Dq 1024
#define Fq 2048
#define Nq 32
#define Pq 4
#define Sq 128   // N*P slots
#define KV 4     // split-K factor for xs stage

// ---------------- scratch (device globals; no allocation allowed) ----------
__device__ float g_logits[Bq * Mq * Sq];        // 8 MB   (B,M,S)
__device__ float g_dispatch[Bq * Mq * Sq];      // 8 MB   (B,M,S)
__device__ float g_combine[Bq * Mq * Sq];       // 8 MB   (B,M,S)
__device__ float g_xs[Bq * Sq * Dq];            // 4 MB   (B,S,D)
__device__ float g_xs_part[KV * Bq * Sq * Dq];  // 16 MB  (KV,B,S,D)
__device__ float g_h[Bq * Sq * Fq];             // 8 MB   (B,S,F)
__device__ float g_y[Bq * Sq * Dq];             // 4 MB   (B,S,D)

// float -> tf32 (round-to-nearest) kept in a 32-bit register
__device__ __forceinline__ uint32_t f2tf32(float f) {
    uint32_t r;
    asm("cvt.rna.tf32.f32 %0, %1;" : "=r"(r) : "f"(f));
    return r;
}

// One KC=16 chunk of warp-tile MMA work.
// As: [k][m] with row stride AST (uint32 elems), Bs: [k][n] stride BST.
// acc[MT][NT][4] accumulators, m16n8k8 tf32 mma.
template <int MT, int NT, int AST, int BST>
__device__ __forceinline__ void mma_chunk(const uint32_t* __restrict__ As,
                                          const uint32_t* __restrict__ Bs,
                                          int mbase, int nbase,
                                          float (*acc)[NT][4]) {
    int lane = threadIdx.x & 31;
    int g = lane >> 2, tg = lane & 3;
#pragma unroll
    for (int ks = 0; ks < 2; ks++) {
        uint32_t a[MT][4], b[NT][2];
#pragma unroll
        for (int i = 0; i < MT; i++) {
            const uint32_t* p = As + (ks * 8 + tg) * AST + mbase + i * 16 + g;
            a[i][0] = p[0];
            a[i][1] = p[8];
            a[i][2] = p[4 * AST];
            a[i][3] = p[4 * AST + 8];
        }
#pragma unroll
        for (int j = 0; j < NT; j++) {
            const uint32_t* p = Bs + (ks * 8 + tg) * BST + nbase + j * 8 + g;
            b[j][0] = p[0];
            b[j][1] = p[4 * BST];
        }
#pragma unroll
        for (int i = 0; i < MT; i++)
#pragma unroll
            for (int j = 0; j < NT; j++)
                asm volatile(
                    "mma.sync.aligned.m16n8k8.row.col.f32.tf32.tf32.f32 "
                    "{%0,%1,%2,%3},{%4,%5,%6,%7},{%8,%9},{%0,%1,%2,%3};\n"
                    : "+f"(acc[i][j][0]), "+f"(acc[i][j][1]),
                      "+f"(acc[i][j][2]), "+f"(acc[i][j][3])
                    : "r"(a[i][0]), "r"(a[i][1]), "r"(a[i][2]), "r"(a[i][3]),
                      "r"(b[j][0]), "r"(b[j][1]));
    }
}

// ============ 1) logits[r,s] = sum_d x[r,d] * phi[d,s], r = b*M+m ==========
// BM=64 BN=64, block 128 (warps 2x2 -> WM=32 WN=32, MT=2 NT=4). grid (256,2).
__global__ void __launch_bounds__(128) logits_mma(const float* __restrict__ x,
                                                  const float* __restrict__ phi) {
    const int r0 = blockIdx.x * 64;
    const int s0 = blockIdx.y * 64;
    __shared__ uint32_t As[2][16][72];
    __shared__ uint32_t Bs[2][16][72];

    int tid = threadIdx.x, warp = tid >> 5, lane = tid & 31;
    int mbase = (warp >> 1) * 32, nbase = (warp & 1) * 32;
    float acc[2][4][4] = {};

    const float* xb = x + (size_t)r0 * Dq;
    const int ar = tid >> 1, akc = (tid & 1) * 8;
    const int bk = tid >> 3, bc = (tid & 7) * 8;

    float4 ra[2], rb[2];
    const int NC = Dq / 16;

    // prologue: chunk 0
    ra[0] = *(const float4*)&xb[(size_t)ar * Dq + akc];
    ra[1] = *(const float4*)&xb[(size_t)ar * Dq + akc + 4];
    rb[0] = *(const float4*)&phi[(size_t)bk * Sq + s0 + bc];
    rb[1] = *(const float4*)&phi[(size_t)bk * Sq + s0 + bc + 4];
#pragma unroll
    for (int j = 0; j < 4; j++) {
        As[0][akc + j][ar] = f2tf32((&ra[0].x)[j]);
        As[0][akc + 4 + j][ar] = f2tf32((&ra[1].x)[j]);
    }
    *(uint4*)&Bs[0][bk][bc] = make_uint4(f2tf32(rb[0].x), f2tf32(rb[0].y),
                                         f2tf32(rb[0].z), f2tf32(rb[0].w));
    *(uint4*)&Bs[0][bk][bc + 4] = make_uint4(f2tf32(rb[1].x), f2tf32(rb[1].y),
                                             f2tf32(rb[1].z), f2tf32(rb[1].w));
    __syncthreads();

#pragma unroll 2
    for (int c = 0; c < NC; c++) {
        if (c + 1 < NC) {
            int k0 = (c + 1) * 16;
            ra[0] = *(const float4*)&xb[(size_t)ar * Dq + k0 + akc];
            ra[1] = *(const float4*)&xb[(size_t)ar * Dq + k0 + akc + 4];
            rb[0] = *(const float4*)&phi[(size_t)(k0 + bk) * Sq + s0 + bc];
            rb[1] = *(const float4*)&phi[(size_t)(k0 + bk) * Sq + s0 + bc + 4];
        }
        mma_chunk<2, 4, 72, 72>(&As[c & 1][0][0], &Bs[c & 1][0][0], mbase, nbase, acc);
        if (c + 1 < NC) {
            int nb = (c + 1) & 1;
#pragma unroll
            for (int j = 0; j < 4; j++) {
                As[nb][akc + j][ar] = f2tf32((&ra[0].x)[j]);
                As[nb][akc + 4 + j][ar] = f2tf32((&ra[1].x)[j]);
            }
            *(uint4*)&Bs[nb][bk][bc] = make_uint4(f2tf32(rb[0].x), f2tf32(rb[0].y),
                                                  f2tf32(rb[0].z), f2tf32(rb[0].w));
            *(uint4*)&Bs[nb][bk][bc + 4] = make_uint4(f2tf32(rb[1].x), f2tf32(rb[1].y),
                                                      f2tf32(rb[1].z), f2tf32(rb[1].w));
        }
        __syncthreads();
    }

    int g = lane >> 2, tg = lane & 3;
    float* lb = g_logits + (size_t)r0 * Sq + s0;
#pragma unroll
    for (int i = 0; i < 2; i++)
#pragma unroll
        for (int j = 0; j < 4; j++) {
            int row = mbase + i * 16 + g, col = nbase + j * 8 + tg * 2;
            *(float2*)&lb[(size_t)row * Sq + col] = make_float2(acc[i][j][0], acc[i][j][1]);
            *(float2*)&lb[(size_t)(row + 8) * Sq + col] = make_float2(acc[i][j][2], acc[i][j][3]);
        }
}

// ============ 2a) combine = softmax over S per (b,m) =======================
__global__ void combine_kernel() {
    int token = blockIdx.x * 8 + (threadIdx.x >> 5);
    int lane = threadIdx.x & 31;
    const float* lp = g_logits + (size_t)token * Sq;

    float v[4];
    float mx = -1e30f;
#pragma unroll
    for (int j = 0; j < 4; j++) {
        v[j] = lp[lane + j * 32];
        mx = fmaxf(mx, v[j]);
    }
#pragma unroll
    for (int off = 16; off > 0; off >>= 1)
        mx = fmaxf(mx, __shfl_xor_sync(0xffffffffu, mx, off));

    float e[4];
    float sum = 0.f;
#pragma unroll
    for (int j = 0; j < 4; j++) {
        e[j] = expf(v[j] - mx);
        sum += e[j];
    }
#pragma unroll
    for (int off = 16; off > 0; off >>= 1)
        sum += __shfl_xor_sync(0xffffffffu, sum, off);

    float inv = 1.f / sum;
    float* cp = g_combine + (size_t)token * Sq;
#pragma unroll
    for (int j = 0; j < 4; j++) cp[lane + j * 32] = e[j] * inv;
}

// ============ 2b) dispatch = softmax over M per (b,s) ======================
__global__ void dispatch_kernel() {
    int b = blockIdx.y;
    int s = blockIdx.x * 32 + threadIdx.x;
    int tx = threadIdx.x, ty = threadIdx.y;

    __shared__ float red[32][33];

    const float* lp = g_logits + (size_t)b * Mq * Sq + s;

    float mx = -1e30f;
    for (int m = ty; m < Mq; m += 32) mx = fmaxf(mx, lp[(size_t)m * Sq]);
    red[ty][tx] = mx;
    __syncthreads();
    for (int off = 16; off > 0; off >>= 1) {
        if (ty < off) red[ty][tx] = fmaxf(red[ty][tx], red[ty + off][tx]);
        __syncthreads();
    }
    mx = red[0][tx];
    __syncthreads();

    float sum = 0.f;
    for (int m = ty; m < Mq; m += 32) sum += expf(lp[(size_t)m * Sq] - mx);
    red[ty][tx] = sum;
    __syncthreads();
    for (int off = 16; off > 0; off >>= 1) {
        if (ty < off) red[ty][tx] += red[ty + off][tx];
        __syncthreads();
    }
    float inv = 1.f / red[0][tx];

    float* dp = g_dispatch + (size_t)b * Mq * Sq + s;
    for (int m = ty; m < Mq; m += 32)
        dp[(size_t)m * Sq] = expf(lp[(size_t)m * Sq] - mx) * inv;
}

// ============ 3) xs partials, split-K over M ===============================
// BM=64(s) BN=128(d), block 256 (warps 2x4, MT=2 NT=4). grid (8, 2, B*KV).
__global__ void __launch_bounds__(256) xs_mma(const float* __restrict__ x) {
    const int b = blockIdx.z >> 2;
    const int kv = blockIdx.z & 3;
    const int s0 = blockIdx.y * 64;
    const int d0 = blockIdx.x * 128;
    const int mk = kv * (Mq / KV);
    __shared__ uint32_t As[2][16][72];
    __shared__ uint32_t Bs[2][16][136];

    int tid = threadIdx.x, warp = tid >> 5, lane = tid & 31;
    int mbase = (warp >> 2) * 32, nbase = (warp & 3) * 32;
    float acc[2][4][4] = {};

    const int ak = tid >> 4, ac = (tid & 15) * 4;

    float4 ra, rb[2];
    const int NC = (Mq / KV) / 16;  // 32

    ra = *(const float4*)&g_dispatch[((size_t)b * Mq + mk + ak) * Sq + s0 + ac];
#pragma unroll
    for (int i = 0; i < 2; i++) {
        int f = tid + i * 256;
        rb[i] = *(const float4*)&x[((size_t)b * Mq + mk + (f >> 5)) * Dq + d0 + (f & 31) * 4];
    }
    *(uint4*)&As[0][ak][ac] = make_uint4(f2tf32(ra.x), f2tf32(ra.y), f2tf32(ra.z), f2tf32(ra.w));
#pragma unroll
    for (int i = 0; i < 2; i++) {
        int f = tid + i * 256;
        *(uint4*)&Bs[0][f >> 5][(f & 31) * 4] =
            make_uint4(f2tf32(rb[i].x), f2tf32(rb[i].y), f2tf32(rb[i].z), f2tf32(rb[i].w));
    }
    __syncthreads();

#pragma unroll 2
    for (int c = 0; c < NC; c++) {
        if (c + 1 < NC) {
            int k0 = mk + (c + 1) * 16;
            ra = *(const float4*)&g_dispatch[((size_t)b * Mq + k0 + ak) * Sq + s0 + ac];
#pragma unroll
            for (int i = 0; i < 2; i++) {
                int f = tid + i * 256;
                rb[i] = *(const float4*)&x[((size_t)b * Mq + k0 + (f >> 5)) * Dq + d0 + (f & 31) * 4];
            }
        }
        mma_chunk<2, 4, 72, 136>(&As[c & 1][0][0], &Bs[c & 1][0][0], mbase, nbase, acc);
        if (c + 1 < NC) {
            int nb = (c + 1) & 1;
            *(uint4*)&As[nb][ak][ac] =
                make_uint4(f2tf32(ra.x), f2tf32(ra.y), f2tf32(ra.z), f2tf32(ra.w));
#pragma unroll
            for (int i = 0; i < 2; i++) {
                int f = tid + i * 256;
                *(uint4*)&Bs[nb][f >> 5][(f & 31) * 4] =
                    make_uint4(f2tf32(rb[i].x), f2tf32(rb[i].y), f2tf32(rb[i].z), f2tf32(rb[i].w));
            }
        }
        __syncthreads();
    }

    int g = lane >> 2, tg = lane & 3;
    float* pp = g_xs_part + ((size_t)kv * Bq + b) * Sq * Dq;
#pragma unroll
    for (int i = 0; i < 2; i++)
#pragma unroll
        for (int j = 0; j < 4; j++) {
            int row = s0 + mbase + i * 16 + g, col = d0 + nbase + j * 8 + tg * 2;
            *(float2*)&pp[(size_t)row * Dq + col] = make_float2(acc[i][j][0], acc[i][j][1]);
            *(float2*)&pp[(size_t)(row + 8) * Dq + col] = make_float2(acc[i][j][2], acc[i][j][3]);
        }
}

// ============ 3b) xs = sum_kv partials =====================================
__global__ void __launch_bounds__(256) xs_reduce() {
    int i = blockIdx.x * 256 + threadIdx.x;  // float4 index
    const int stride = Bq * Sq * Dq / 4;
    const float4* p = (const float4*)g_xs_part;
    float4 a = p[i];
    float4 b = p[i + stride];
    float4 c = p[i + 2 * stride];
    float4 d = p[i + 3 * stride];
    ((float4*)g_xs)[i] = make_float4(a.x + b.x + c.x + d.x, a.y + b.y + c.y + d.y,
                                     a.z + b.z + c.z + d.z, a.w + b.w + c.w + d.w);
}

// ============ 4a) h = relu(xs @ w1 + b1)^2 per expert ======================
// BM=32 BN=128, block 256 (warps 1x8, MT=2 NT=2). grid (16, 32).
__global__ void __launch_bounds__(256) ffn1_mma(const float* __restrict__ w1,
                                                const float* __restrict__ b1) {
    const int n = blockIdx.y;
    const int f0 = blockIdx.x * 128;
    __shared__ uint32_t As[2][16][40];
    __shared__ uint32_t Bs[2][16][136];

    int tid = threadIdx.x, warp = tid >> 5, lane = tid & 31;
    int nbase = warp * 16;
    float acc[2][2][4] = {};

    const int ar = tid >> 2, akc = (tid & 3) * 4;

    float4 ra, rb[2];
    const int NC = Dq / 16;

    if (tid < 128)
        ra = *(const float4*)&g_xs[(((size_t)(ar >> 2)) * Sq + n * 4 + (ar & 3)) * Dq + akc];
#pragma unroll
    for (int i = 0; i < 2; i++) {
        int f = tid + i * 256;
        rb[i] = *(const float4*)&w1[((size_t)n * Dq + (f >> 5)) * Fq + f0 + (f & 31) * 4];
    }
    if (tid < 128) {
#pragma unroll
        for (int j = 0; j < 4; j++) As[0][akc + j][ar] = f2tf32((&ra.x)[j]);
    }
#pragma unroll
    for (int i = 0; i < 2; i++) {
        int f = tid + i * 256;
        *(uint4*)&Bs[0][f >> 5][(f & 31) * 4] =
            make_uint4(f2tf32(rb[i].x), f2tf32(rb[i].y), f2tf32(rb[i].z), f2tf32(rb[i].w));
    }
    __syncthreads();

#pragma unroll 2
    for (int c = 0; c < NC; c++) {
        if (c + 1 < NC) {
            int k0 = (c + 1) * 16;
            if (tid < 128)
                ra = *(const float4*)&g_xs[(((size_t)(ar >> 2)) * Sq + n * 4 + (ar & 3)) * Dq +
                                           k0 + akc];
#pragma unroll
            for (int i = 0; i < 2; i++) {
                int f = tid + i * 256;
                rb[i] = *(const float4*)&w1[((size_t)n * Dq + k0 + (f >> 5)) * Fq +
                                            f0 + (f & 31) * 4];
            }
        }
        mma_chunk<2, 2, 40, 136>(&As[c & 1][0][0], &Bs[c & 1][0][0], 0, nbase, acc);
        if (c + 1 < NC) {
            int nb = (c + 1) & 1;
            if (tid < 128) {
#pragma unroll
                for (int j = 0; j < 4; j++) As[nb][akc + j][ar] = f2tf32((&ra.x)[j]);
            }
#pragma unroll
            for (int i = 0; i < 2; i++) {
                int f = tid + i * 256;
                *(uint4*)&Bs[nb][f >> 5][(f & 31) * 4] =
                    make_uint4(f2tf32(rb[i].x), f2tf32(rb[i].y), f2tf32(rb[i].z), f2tf32(rb[i].w));
            }
        }
        __syncthreads();
    }

    int g = lane >> 2, tg = lane & 3;
#pragma unroll
    for (int i = 0; i < 2; i++)
#pragma unroll
        for (int j = 0; j < 2; j++) {
            int row = i * 16 + g;
            int col = nbase + j * 8 + tg * 2;
#pragma unroll
            for (int half = 0; half < 2; half++) {
                int rr = row + half * 8;
                float h0 = acc[i][j][half * 2 + 0] + b1[(size_t)n * Fq + f0 + col];
                float h1 = acc[i][j][half * 2 + 1] + b1[(size_t)n * Fq + f0 + col + 1];
                h0 = fmaxf(h0, 0.f); h1 = fmaxf(h1, 0.f);
                float* hp = &g_h[(((size_t)(rr >> 2)) * Sq + n * 4 + (rr & 3)) * Fq + f0 + col];
                *(float2*)hp = make_float2(h0 * h0, h1 * h1);
            }
        }
}

// ============ 4b) y = h @ w2 + b2 per expert ===============================
// BM=32 BN=64, block 256 (warps 1x8, MT=2 NT=1). grid (16, 32).
__global__ void __launch_bounds__(256) ffn2_mma(const float* __restrict__ w2,
                                                const float* __restrict__ b2) {
    const int n = blockIdx.y;
    const int d0 = blockIdx.x * 64;
    __shared__ uint32_t As[2][16][40];
    __shared__ uint32_t Bs[2][16][72];

    int tid = threadIdx.x, warp = tid >> 5, lane = tid & 31;
    int nbase = warp * 8;
    float acc[2][1][4] = {};

    const int ar = tid >> 2, akc = (tid & 3) * 4;
    const int bk = tid >> 4, bc = (tid & 15) * 4;

    float4 ra, rb;
    const int NC = Fq / 16;

    if (tid < 128)
        ra = *(const float4*)&g_h[(((size_t)(ar >> 2)) * Sq + n * 4 + (ar & 3)) * Fq + akc];
    rb = *(const float4*)&w2[((size_t)n * Fq + bk) * Dq + d0 + bc];
    if (tid < 128) {
#pragma unroll
        for (int j = 0; j < 4; j++) As[0][akc + j][ar] = f2tf32((&ra.x)[j]);
    }
    *(uint4*)&Bs[0][bk][bc] = make_uint4(f2tf32(rb.x), f2tf32(rb.y), f2tf32(rb.z), f2tf32(rb.w));
    __syncthreads();

#pragma unroll 2
    for (int c = 0; c < NC; c++) {
        if (c + 1 < NC) {
            int k0 = (c + 1) * 16;
            if (tid < 128)
                ra = *(const float4*)&g_h[(((size_t)(ar >> 2)) * Sq + n * 4 + (ar & 3)) * Fq +
                                          k0 + akc];
            rb = *(const float4*)&w2[((size_t)n * Fq + k0 + bk) * Dq + d0 + bc];
        }
        mma_chunk<2, 1, 40, 72>(&As[c & 1][0][0], &Bs[c & 1][0][0], 0, nbase, acc);
        if (c + 1 < NC) {
            int nb = (c + 1) & 1;
            if (tid < 128) {
#pragma unroll
                for (int j = 0; j < 4; j++) As[nb][akc + j][ar] = f2tf32((&ra.x)[j]);
            }
            *(uint4*)&Bs[nb][bk][bc] =
                make_uint4(f2tf32(rb.x), f2tf32(rb.y), f2tf32(rb.z), f2tf32(rb.w));
        }
        __syncthreads();
    }

    int g = lane >> 2, tg = lane & 3;
#pragma unroll
    for (int i = 0; i < 2; i++) {
        int row = i * 16 + g;
        int col = d0 + nbase + tg * 2;
#pragma unroll
        for (int half = 0; half < 2; half++) {
            int rr = row + half * 8;
            float y0 = acc[i][0][half * 2 + 0] + b2[(size_t)n * Dq + col];
            float y1 = acc[i][0][half * 2 + 1] + b2[(size_t)n * Dq + col + 1];
            float* yp = &g_y[(((size_t)(rr >> 2)) * Sq + n * 4 + (rr & 3)) * Dq + col];
            *(float2*)yp = make_float2(y0, y1);
        }
    }
}

// ============ 5) out[b,m,d] = sum_s combine[b,m,s] * y[b,s,d] ==============
// BM=128 BN=128, block 256 (warps 2x4, MT=4 NT=4). grid (8, 16, 8). K=128.
__global__ void __launch_bounds__(256) out_mma(float* __restrict__ out) {
    const int b = blockIdx.z;
    const int m0 = blockIdx.y * 128;
    const int d0 = blockIdx.x * 128;
    __shared__ uint32_t As[2][16][136];
    __shared__ uint32_t Bs[2][16][136];

    int tid = threadIdx.x, warp = tid >> 5, lane = tid & 31;
    int mbase = (warp >> 2) * 64, nbase = (warp & 3) * 32;
    float acc[4][4][4] = {};

    const float* cb = g_combine + ((size_t)b * Mq + m0) * Sq;
    float4 ra[2], rb[2];
    const int NC = Sq / 16;  // 8

#pragma unroll
    for (int i = 0; i < 2; i++) {
        int f = tid + i * 256;
        ra[i] = *(const float4*)&cb[(size_t)(f >> 2) * Sq + (f & 3) * 4];
        rb[i] = *(const float4*)&g_y[((size_t)b * Sq + (f >> 5)) * Dq + d0 + (f & 31) * 4];
    }
#pragma unroll
    for (int i = 0; i < 2; i++) {
        int f = tid + i * 256;
        int r = f >> 2, cc = f & 3;
#pragma unroll
        for (int j = 0; j < 4; j++) As[0][cc * 4 + j][r] = f2tf32((&ra[i].x)[j]);
        *(uint4*)&Bs[0][f >> 5][(f & 31) * 4] =
            make_uint4(f2tf32(rb[i].x), f2tf32(rb[i].y), f2tf32(rb[i].z), f2tf32(rb[i].w));
    }
    __syncthreads();

#pragma unroll 2
    for (int c = 0; c < NC; c++) {
        if (c + 1 < NC) {
            int k0 = (c + 1) * 16;
#pragma unroll
            for (int i = 0; i < 2; i++) {
                int f = tid + i * 256;
                ra[i] = *(const float4*)&cb[(size_t)(f >> 2) * Sq + k0 + (f & 3) * 4];
                rb[i] = *(const float4*)&g_y[((size_t)b * Sq + k0 + (f >> 5)) * Dq +
                                             d0 + (f & 31) * 4];
            }
        }
        mma_chunk<4, 4, 136, 136>(&As[c & 1][0][0], &Bs[c & 1][0][0], mbase, nbase, acc);
        if (c + 1 < NC) {
            int nb = (c + 1) & 1;
#pragma unroll
            for (int i = 0; i < 2; i++) {
                int f = tid + i * 256;
                int r = f >> 2, cc = f & 3;
#pragma unroll
                for (int j = 0; j < 4; j++) As[nb][cc * 4 + j][r] = f2tf32((&ra[i].x)[j]);
                *(uint4*)&Bs[nb][f >> 5][(f & 31) * 4] =
                    make_uint4(f2tf32(rb[i].x), f2tf32(rb[i].y), f2tf32(rb[i].z), f2tf32(rb[i].w));
            }
        }
        __syncthreads();
    }

    int g = lane >> 2, tg = lane & 3;
    float* ob = out + ((size_t)b * Mq + m0) * Dq + d0;
#pragma unroll
    for (int i = 0; i < 4; i++)
#pragma unroll
        for (int j = 0; j < 4; j++) {
            int row = mbase + i * 16 + g, col = nbase + j * 8 + tg * 2;
            *(float2*)&ob[(size_t)row * Dq + col] = make_float2(acc[i][j][0], acc[i][j][1]);
            *(float2*)&ob[(size_t)(row + 8) * Dq + col] = make_float2(acc[i][j][2], acc[i][j][3]);
        }
}

// ---------------------------------------------------------------------------
extern "C" void kernel_launch(void* const* d_in, const int* in_sizes, int n_in,
                              void* d_out, int out_size) {
    const float* x   = (const float*)d_in[0];
    const float* phi = (const float*)d_in[1];
    const float* w1  = (const float*)d_in[2];
    const float* b1  = (const float*)d_in[3];
    const float* w2  = (const float*)d_in[4];
    const float* b2  = (const float*)d_in[5];
    float* out = (float*)d_out;

    logits_mma<<<dim3((Bq * Mq) / 64, Sq / 64), 128>>>(x, phi);
    combine_kernel<<<(Bq * Mq) / 8, 256>>>();
    dispatch_kernel<<<dim3(Sq / 32, Bq), dim3(32, 32)>>>();
    xs_mma<<<dim3(Dq / 128, Sq / 64, Bq * KV), 256>>>(x);
    xs_reduce<<<(Bq * Sq * Dq / 4) / 256, 256>>>();
    ffn1_mma<<<dim3(Fq / 128, Nq), 256>>>(w1, b1);
    ffn2_mma<<<dim3(Dq / 64, Nq), 256>>>(w2, b2);
    out_mma<<<dim3(Dq / 128, Mq / 128, Bq), 256>>>(out);
}

// round 4
// speedup vs baseline: 5.3625x; 1.2927x over previous
#include <cuda_runtime.h>
#include <math.h>
#include <stdint.h>

#define Bq 8
#define Mq 2048
#define Dq 1024
#define Fq 2048
#define Nq 32
#define Pq 4
#define Sq 128   // N*P slots
#define KV 4     // split-K factor for xs stage

// ---------------- scratch (device globals; no allocation allowed) ----------
__device__ float g_logits[Bq * Mq * Sq];        // 8 MB   (B,M,S)
__device__ float g_dispatch[Bq * Mq * Sq];      // 8 MB   (B,M,S)
__device__ float g_combine[Bq * Mq * Sq];       // 8 MB   (B,M,S)
__device__ float g_xs[Bq * Sq * Dq];            // 4 MB   (B,S,D)
__device__ float g_xs_part[KV * Bq * Sq * Dq];  // 16 MB  (KV,B,S,D)
__device__ float g_h[Bq * Sq * Fq];             // 8 MB   (B,S,F)
__device__ float g_y[Bq * Sq * Dq];             // 4 MB   (B,S,D)

// float -> tf32 (round-to-nearest) kept in a 32-bit register
__device__ __forceinline__ uint32_t f2tf32(float f) {
    uint32_t r;
    asm("cvt.rna.tf32.f32 %0, %1;" : "=r"(r) : "f"(f));
    return r;
}

__device__ __forceinline__ uint32_t smem_u32(const void* p) {
    return (uint32_t)__cvta_generic_to_shared(p);
}
__device__ __forceinline__ void cp16(uint32_t dst, const void* src) {
    asm volatile("cp.async.cg.shared.global [%0], [%1], 16;" :: "r"(dst), "l"(src));
}
__device__ __forceinline__ void cp_commit() {
    asm volatile("cp.async.commit_group;");
}
template <int N>
__device__ __forceinline__ void cp_wait() {
    asm volatile("cp.async.wait_group %0;" :: "n"(N));
}

// ---- MMA on one K=16 chunk. A fragments cvt.rna'd; B fragments raw f32 bits
// (mma.tf32 uses the high 19 bits = truncation).

// A stored k-major: As[k][m], row stride AST (mod 32 == 8 for no conflicts)
template <int MT, int NT, int AST, int BST>
__device__ __forceinline__ void mma_akm(const float* __restrict__ As,
                                        const float* __restrict__ Bs,
                                        int mbase, int nbase, float (*acc)[NT][4]) {
    int lane = threadIdx.x & 31;
    int g = lane >> 2, tg = lane & 3;
#pragma unroll
    for (int ks = 0; ks < 2; ks++) {
        uint32_t a[MT][4], b[NT][2];
#pragma unroll
        for (int i = 0; i < MT; i++) {
            const float* p = As + (ks * 8 + tg) * AST + mbase + i * 16 + g;
            a[i][0] = f2tf32(p[0]);
            a[i][1] = f2tf32(p[8]);
            a[i][2] = f2tf32(p[4 * AST]);
            a[i][3] = f2tf32(p[4 * AST + 8]);
        }
#pragma unroll
        for (int j = 0; j < NT; j++) {
            const uint32_t* p = (const uint32_t*)Bs + (ks * 8 + tg) * BST + nbase + j * 8 + g;
            b[j][0] = p[0];
            b[j][1] = p[4 * BST];
        }
#pragma unroll
        for (int i = 0; i < MT; i++)
#pragma unroll
            for (int j = 0; j < NT; j++)
                asm volatile(
                    "mma.sync.aligned.m16n8k8.row.col.f32.tf32.tf32.f32 "
                    "{%0,%1,%2,%3},{%4,%5,%6,%7},{%8,%9},{%0,%1,%2,%3};\n"
                    : "+f"(acc[i][j][0]), "+f"(acc[i][j][1]),
                      "+f"(acc[i][j][2]), "+f"(acc[i][j][3])
                    : "r"(a[i][0]), "r"(a[i][1]), "r"(a[i][2]), "r"(a[i][3]),
                      "r"(b[j][0]), "r"(b[j][1]));
    }
}

// A stored m-major: As[m][k], row stride AST=20 (g*20+tg distinct mod 32)
template <int MT, int NT, int AST, int BST>
__device__ __forceinline__ void mma_amk(const float* __restrict__ As,
                                        const float* __restrict__ Bs,
                                        int mbase, int nbase, float (*acc)[NT][4]) {
    int lane = threadIdx.x & 31;
    int g = lane >> 2, tg = lane & 3;
#pragma unroll
    for (int ks = 0; ks < 2; ks++) {
        uint32_t a[MT][4], b[NT][2];
#pragma unroll
        for (int i = 0; i < MT; i++) {
            const float* p = As + (size_t)(mbase + i * 16 + g) * AST + ks * 8 + tg;
            a[i][0] = f2tf32(p[0]);
            a[i][1] = f2tf32(p[8 * AST]);
            a[i][2] = f2tf32(p[4]);
            a[i][3] = f2tf32(p[8 * AST + 4]);
        }
#pragma unroll
        for (int j = 0; j < NT; j++) {
            const uint32_t* p = (const uint32_t*)Bs + (ks * 8 + tg) * BST + nbase + j * 8 + g;
            b[j][0] = p[0];
            b[j][1] = p[4 * BST];
        }
#pragma unroll
        for (int i = 0; i < MT; i++)
#pragma unroll
            for (int j = 0; j < NT; j++)
                asm volatile(
                    "mma.sync.aligned.m16n8k8.row.col.f32.tf32.tf32.f32 "
                    "{%0,%1,%2,%3},{%4,%5,%6,%7},{%8,%9},{%0,%1,%2,%3};\n"
                    : "+f"(acc[i][j][0]), "+f"(acc[i][j][1]),
                      "+f"(acc[i][j][2]), "+f"(acc[i][j][3])
                    : "r"(a[i][0]), "r"(a[i][1]), "r"(a[i][2]), "r"(a[i][3]),
                      "r"(b[j][0]), "r"(b[j][1]));
    }
}

// ============ 1) logits[r,s] = sum_d x[r,d] * phi[d,s], r = b*M+m ==========
// BM=64 BN=64, block 128 (warps 2x2, MT=2 NT=4). 4-stage cp.async. grid (256,2).
__global__ void __launch_bounds__(128) logits_mma(const float* __restrict__ x,
                                                  const float* __restrict__ phi) {
    const int r0 = blockIdx.x * 64;
    const int s0 = blockIdx.y * 64;
    __shared__ float As[4][64 * 20];
    __shared__ float Bs[4][16 * 72];

    int tid = threadIdx.x, warp = tid >> 5, lane = tid & 31;
    int mbase = (warp >> 1) * 32, nbase = (warp & 1) * 32;
    float acc[2][4][4] = {};

    const float* xb = x + (size_t)r0 * Dq;
    const int NC = Dq / 16;  // 64

    auto issue = [&](int c) {
        int k0 = c * 16, st = c & 3;
#pragma unroll
        for (int u = 0; u < 2; u++) {
            int idx = tid + u * 128;
            int row = idx >> 2, kc = (idx & 3) * 4;
            cp16(smem_u32(&As[st][row * 20 + kc]), &xb[(size_t)row * Dq + k0 + kc]);
            int kk = idx >> 4, sc = (idx & 15) * 4;
            cp16(smem_u32(&Bs[st][kk * 72 + sc]), &phi[(size_t)(k0 + kk) * Sq + s0 + sc]);
        }
        cp_commit();
    };
    issue(0); issue(1); issue(2);
#pragma unroll 1
    for (int c = 0; c < NC; c++) {
        cp_wait<2>();
        __syncthreads();
        if (c + 3 < NC) issue(c + 3); else cp_commit();
        mma_amk<2, 4, 20, 72>(As[c & 3], Bs[c & 3], mbase, nbase, acc);
    }

    int g = lane >> 2, tg = lane & 3;
    float* lb = g_logits + (size_t)r0 * Sq + s0;
#pragma unroll
    for (int i = 0; i < 2; i++)
#pragma unroll
        for (int j = 0; j < 4; j++) {
            int row = mbase + i * 16 + g, col = nbase + j * 8 + tg * 2;
            *(float2*)&lb[(size_t)row * Sq + col] = make_float2(acc[i][j][0], acc[i][j][1]);
            *(float2*)&lb[(size_t)(row + 8) * Sq + col] = make_float2(acc[i][j][2], acc[i][j][3]);
        }
}

// ============ 2a) combine = softmax over S per (b,m) =======================
__global__ void combine_kernel() {
    int token = blockIdx.x * 8 + (threadIdx.x >> 5);
    int lane = threadIdx.x & 31;
    const float* lp = g_logits + (size_t)token * Sq;

    float v[4];
    float mx = -1e30f;
#pragma unroll
    for (int j = 0; j < 4; j++) {
        v[j] = lp[lane + j * 32];
        mx = fmaxf(mx, v[j]);
    }
#pragma unroll
    for (int off = 16; off > 0; off >>= 1)
        mx = fmaxf(mx, __shfl_xor_sync(0xffffffffu, mx, off));

    float e[4];
    float sum = 0.f;
#pragma unroll
    for (int j = 0; j < 4; j++) {
        e[j] = expf(v[j] - mx);
        sum += e[j];
    }
#pragma unroll
    for (int off = 16; off > 0; off >>= 1)
        sum += __shfl_xor_sync(0xffffffffu, sum, off);

    float inv = 1.f / sum;
    float* cp = g_combine + (size_t)token * Sq;
#pragma unroll
    for (int j = 0; j < 4; j++) cp[lane + j * 32] = e[j] * inv;
}

// ============ 2b) dispatch = softmax over M per (b,s) ======================
__global__ void dispatch_kernel() {
    int b = blockIdx.y;
    int s = blockIdx.x * 32 + threadIdx.x;
    int tx = threadIdx.x, ty = threadIdx.y;

    __shared__ float red[32][33];

    const float* lp = g_logits + (size_t)b * Mq * Sq + s;

    float mx = -1e30f;
    for (int m = ty; m < Mq; m += 32) mx = fmaxf(mx, lp[(size_t)m * Sq]);
    red[ty][tx] = mx;
    __syncthreads();
    for (int off = 16; off > 0; off >>= 1) {
        if (ty < off) red[ty][tx] = fmaxf(red[ty][tx], red[ty + off][tx]);
        __syncthreads();
    }
    mx = red[0][tx];
    __syncthreads();

    float sum = 0.f;
    for (int m = ty; m < Mq; m += 32) sum += expf(lp[(size_t)m * Sq] - mx);
    red[ty][tx] = sum;
    __syncthreads();
    for (int off = 16; off > 0; off >>= 1) {
        if (ty < off) red[ty][tx] += red[ty + off][tx];
        __syncthreads();
    }
    float inv = 1.f / red[0][tx];

    float* dp = g_dispatch + (size_t)b * Mq * Sq + s;
    for (int m = ty; m < Mq; m += 32)
        dp[(size_t)m * Sq] = expf(lp[(size_t)m * Sq] - mx) * inv;
}

// ============ 3) xs partials, split-K over M ===============================
// BM=64(s) BN=128(d), block 256 (warps 2x4, MT=2 NT=4). 3-stage. grid (8,2,B*KV).
// A = dispatch slice is k-major in global -> smem [k][s].
__global__ void __launch_bounds__(256) xs_mma(const float* __restrict__ x) {
    const int b = blockIdx.z >> 2;
    const int kv = blockIdx.z & 3;
    const int s0 = blockIdx.y * 64;
    const int d0 = blockIdx.x * 128;
    const int mk = kv * (Mq / KV);
    __shared__ float As[3][16 * 72];
    __shared__ float Bs[3][16 * 136];

    int tid = threadIdx.x, warp = tid >> 5, lane = tid & 31;
    int mbase = (warp >> 2) * 32, nbase = (warp & 3) * 32;
    float acc[2][4][4] = {};

    const int NC = (Mq / KV) / 16;  // 32

    auto issue = [&](int c) {
        int k0 = mk + c * 16, st = c % 3;
        {
            int kk = tid >> 4, sc = (tid & 15) * 4;
            cp16(smem_u32(&As[st][kk * 72 + sc]),
                 &g_dispatch[((size_t)b * Mq + k0 + kk) * Sq + s0 + sc]);
        }
#pragma unroll
        for (int u = 0; u < 2; u++) {
            int idx = tid + u * 256;
            int kk = idx >> 5, dc = (idx & 31) * 4;
            cp16(smem_u32(&Bs[st][kk * 136 + dc]),
                 &x[((size_t)b * Mq + k0 + kk) * Dq + d0 + dc]);
        }
        cp_commit();
    };
    issue(0); issue(1);
#pragma unroll 1
    for (int c = 0; c < NC; c++) {
        cp_wait<1>();
        __syncthreads();
        if (c + 2 < NC) issue(c + 2); else cp_commit();
        mma_akm<2, 4, 72, 136>(As[c % 3], Bs[c % 3], mbase, nbase, acc);
    }

    int g = lane >> 2, tg = lane & 3;
    float* pp = g_xs_part + ((size_t)kv * Bq + b) * Sq * Dq;
#pragma unroll
    for (int i = 0; i < 2; i++)
#pragma unroll
        for (int j = 0; j < 4; j++) {
            int row = s0 + mbase + i * 16 + g, col = d0 + nbase + j * 8 + tg * 2;
            *(float2*)&pp[(size_t)row * Dq + col] = make_float2(acc[i][j][0], acc[i][j][1]);
            *(float2*)&pp[(size_t)(row + 8) * Dq + col] = make_float2(acc[i][j][2], acc[i][j][3]);
        }
}

// ============ 3b) xs = sum_kv partials =====================================
__global__ void __launch_bounds__(256) xs_reduce() {
    int i = blockIdx.x * 256 + threadIdx.x;  // float4 index
    const int stride = Bq * Sq * Dq / 4;
    const float4* p = (const float4*)g_xs_part;
    float4 a = p[i];
    float4 b = p[i + stride];
    float4 c = p[i + 2 * stride];
    float4 d = p[i + 3 * stride];
    ((float4*)g_xs)[i] = make_float4(a.x + b.x + c.x + d.x, a.y + b.y + c.y + d.y,
                                     a.z + b.z + c.z + d.z, a.w + b.w + c.w + d.w);
}

// ============ 4a) h = relu(xs @ w1 + b1)^2 per expert ======================
// BM=32 BN=128, block 256 (warps 1x8, MT=2 NT=2). 4-stage. grid (16, 32).
__global__ void __launch_bounds__(256) ffn1_mma(const float* __restrict__ w1,
                                                const float* __restrict__ b1) {
    const int n = blockIdx.y;
    const int f0 = blockIdx.x * 128;
    __shared__ float As[4][32 * 20];
    __shared__ float Bs[4][16 * 136];

    int tid = threadIdx.x, warp = tid >> 5, lane = tid & 31;
    int nbase = warp * 16;
    float acc[2][2][4] = {};

    const int NC = Dq / 16;  // 64

    auto issue = [&](int c) {
        int k0 = c * 16, st = c & 3;
        if (tid < 128) {
            int row = tid >> 2, kc = (tid & 3) * 4;
            cp16(smem_u32(&As[st][row * 20 + kc]),
                 &g_xs[(((size_t)(row >> 2)) * Sq + n * 4 + (row & 3)) * Dq + k0 + kc]);
        }
#pragma unroll
        for (int u = 0; u < 2; u++) {
            int idx = tid + u * 256;
            int kk = idx >> 5, fc = (idx & 31) * 4;
            cp16(smem_u32(&Bs[st][kk * 136 + fc]),
                 &w1[((size_t)n * Dq + k0 + kk) * Fq + f0 + fc]);
        }
        cp_commit();
    };
    issue(0); issue(1); issue(2);
#pragma unroll 1
    for (int c = 0; c < NC; c++) {
        cp_wait<2>();
        __syncthreads();
        if (c + 3 < NC) issue(c + 3); else cp_commit();
        mma_amk<2, 2, 20, 136>(As[c & 3], Bs[c & 3], 0, nbase, acc);
    }

    int g = lane >> 2, tg = lane & 3;
#pragma unroll
    for (int i = 0; i < 2; i++)
#pragma unroll
        for (int j = 0; j < 2; j++) {
            int row = i * 16 + g;
            int col = nbase + j * 8 + tg * 2;
#pragma unroll
            for (int half = 0; half < 2; half++) {
                int rr = row + half * 8;
                float h0 = acc[i][j][half * 2 + 0] + b1[(size_t)n * Fq + f0 + col];
                float h1 = acc[i][j][half * 2 + 1] + b1[(size_t)n * Fq + f0 + col + 1];
                h0 = fmaxf(h0, 0.f); h1 = fmaxf(h1, 0.f);
                float* hp = &g_h[(((size_t)(rr >> 2)) * Sq + n * 4 + (rr & 3)) * Fq + f0 + col];
                *(float2*)hp = make_float2(h0 * h0, h1 * h1);
            }
        }
}

// ============ 4b) y = h @ w2 + b2 per expert ===============================
// BM=32 BN=64, block 256 (warps 1x8, MT=2 NT=1). 4-stage. grid (16, 32).
__global__ void __launch_bounds__(256) ffn2_mma(const float* __restrict__ w2,
                                                const float* __restrict__ b2) {
    const int n = blockIdx.y;
    const int d0 = blockIdx.x * 64;
    __shared__ float As[4][32 * 20];
    __shared__ float Bs[4][16 * 72];

    int tid = threadIdx.x, warp = tid >> 5, lane = tid & 31;
    int nbase = warp * 8;
    float acc[2][1][4] = {};

    const int NC = Fq / 16;  // 128

    auto issue = [&](int c) {
        int k0 = c * 16, st = c & 3;
        if (tid < 128) {
            int row = tid >> 2, kc = (tid & 3) * 4;
            cp16(smem_u32(&As[st][row * 20 + kc]),
                 &g_h[(((size_t)(row >> 2)) * Sq + n * 4 + (row & 3)) * Fq + k0 + kc]);
        }
        {
            int kk = tid >> 4, dc = (tid & 15) * 4;
            cp16(smem_u32(&Bs[st][kk * 72 + dc]),
                 &w2[((size_t)n * Fq + k0 + kk) * Dq + d0 + dc]);
        }
        cp_commit();
    };
    issue(0); issue(1); issue(2);
#pragma unroll 1
    for (int c = 0; c < NC; c++) {
        cp_wait<2>();
        __syncthreads();
        if (c + 3 < NC) issue(c + 3); else cp_commit();
        mma_amk<2, 1, 20, 72>(As[c & 3], Bs[c & 3], 0, nbase, acc);
    }

    int g = lane >> 2, tg = lane & 3;
#pragma unroll
    for (int i = 0; i < 2; i++) {
        int row = i * 16 + g;
        int col = d0 + nbase + tg * 2;
#pragma unroll
        for (int half = 0; half < 2; half++) {
            int rr = row + half * 8;
            float y0 = acc[i][0][half * 2 + 0] + b2[(size_t)n * Dq + col];
            float y1 = acc[i][0][half * 2 + 1] + b2[(size_t)n * Dq + col + 1];
            float* yp = &g_y[(((size_t)(rr >> 2)) * Sq + n * 4 + (rr & 3)) * Dq + col];
            *(float2*)yp = make_float2(y0, y1);
        }
    }
}

// ============ 5) out[b,m,d] = sum_s combine[b,m,s] * y[b,s,d] ==============
// BM=128 BN=128, block 256 (warps 2x4, MT=4 NT=4). 2-stage. grid (8,16,8). K=128.
__global__ void __launch_bounds__(256) out_mma(float* __restrict__ out) {
    const int b = blockIdx.z;
    const int m0 = blockIdx.y * 128;
    const int d0 = blockIdx.x * 128;
    __shared__ float As[2][128 * 20];
    __shared__ float Bs[2][16 * 136];

    int tid = threadIdx.x, warp = tid >> 5, lane = tid & 31;
    int mbase = (warp >> 2) * 64, nbase = (warp & 3) * 32;
    float acc[4][4][4] = {};

    const float* cb = g_combine + ((size_t)b * Mq + m0) * Sq;
    const int NC = Sq / 16;  // 8

    auto issue = [&](int c) {
        int k0 = c * 16, st = c & 1;
#pragma unroll
        for (int u = 0; u < 2; u++) {
            int idx = tid + u * 256;
            int row = idx >> 2, kc = (idx & 3) * 4;
            cp16(smem_u32(&As[st][row * 20 + kc]), &cb[(size_t)row * Sq + k0 + kc]);
            int kk = idx >> 5, dc = (idx & 31) * 4;
            cp16(smem_u32(&Bs[st][kk * 136 + dc]),
                 &g_y[((size_t)b * Sq + k0 + kk) * Dq + d0 + dc]);
        }
        cp_commit();
    };
    issue(0);
#pragma unroll 1
    for (int c = 0; c < NC; c++) {
        cp_wait<0>();
        __syncthreads();
        if (c + 1 < NC) issue(c + 1);
        mma_amk<4, 4, 20, 136>(As[c & 1], Bs[c & 1], mbase, nbase, acc);
        __syncthreads();
    }

    int g = lane >> 2, tg = lane & 3;
    float* ob = out + ((size_t)b * Mq + m0) * Dq + d0;
#pragma unroll
    for (int i = 0; i < 4; i++)
#pragma unroll
        for (int j = 0; j < 4; j++) {
            int row = mbase + i * 16 + g, col = nbase + j * 8 + tg * 2;
            *(float2*)&ob[(size_t)row * Dq + col] = make_float2(acc[i][j][0], acc[i][j][1]);
            *(float2*)&ob[(size_t)(row + 8) * Dq + col] = make_float2(acc[i][j][2], acc[i][j][3]);
        }
}

// ---------------------------------------------------------------------------
extern "C" void kernel_launch(void* const* d_in, const int* in_sizes, int n_in,
                              void* d_out, int out_size) {
    const float* x   = (const float*)d_in[0];
    const float* phi = (const float*)d_in[1];
    const float* w1  = (const float*)d_in[2];
    const float* b1  = (const float*)d_in[3];
    const float* w2  = (const float*)d_in[4];
    const float* b2  = (const float*)d_in[5];
    float* out = (float*)d_out;

    logits_mma<<<dim3((Bq * Mq) / 64, Sq / 64), 128>>>(x, phi);
    combine_kernel<<<(Bq * Mq) / 8, 256>>>();
    dispatch_kernel<<<dim3(Sq / 32, Bq), dim3(32, 32)>>>();
    xs_mma<<<dim3(Dq / 128, Sq / 64, Bq * KV), 256>>>(x);
    xs_reduce<<<(Bq * Sq * Dq / 4) / 256, 256>>>();
    ffn1_mma<<<dim3(Fq / 128, Nq), 256>>>(w1, b1);
    ffn2_mma<<<dim3(Dq / 64, Nq), 256>>>(w2, b2);
    out_mma<<<dim3(Dq / 128, Mq / 128, Bq), 256>>>(out);
}

// round 5
// speedup vs baseline: 5.9511x; 1.1098x over previous
#include <cuda_runtime.h>
#include <math.h>
#include <stdint.h>

#define Bq 8
#define Mq 2048
#define Dq 1024
#define Fq 2048
#define Nq 32
#define Pq 4
#define Sq 128   // N*P slots
#define KV 4     // split-K factor for xs stage

// ---------------- scratch (device globals; no allocation allowed) ----------
__device__ float g_logits[Bq * Mq * Sq];        // 8 MB   (B,M,S)
__device__ float g_dispatch[Bq * Mq * Sq];      // 8 MB   (B,M,S)  tf32-rounded
__device__ float g_combine[Bq * Mq * Sq];       // 8 MB   (B,M,S)  tf32-rounded
__device__ float g_xs[Bq * Sq * Dq];            // 4 MB   (B,S,D)  tf32-rounded
__device__ float g_xs_part[KV * Bq * Sq * Dq];  // 16 MB  (KV,B,S,D)
__device__ float g_h[Bq * Sq * Fq];             // 8 MB   (B,S,F)  tf32-rounded
__device__ float g_y[Bq * Sq * Dq];             // 4 MB   (B,S,D)

// float -> tf32 (round-to-nearest) kept in a 32-bit register
__device__ __forceinline__ uint32_t f2tf32(float f) {
    uint32_t r;
    asm("cvt.rna.tf32.f32 %0, %1;" : "=r"(r) : "f"(f));
    return r;
}
__device__ __forceinline__ float round_tf32(float f) {
    return __uint_as_float(f2tf32(f));
}

__device__ __forceinline__ uint32_t smem_u32(const void* p) {
    return (uint32_t)__cvta_generic_to_shared(p);
}
__device__ __forceinline__ void cp16(uint32_t dst, const void* src) {
    asm volatile("cp.async.cg.shared.global [%0], [%1], 16;" :: "r"(dst), "l"(src));
}
__device__ __forceinline__ void cp_commit() {
    asm volatile("cp.async.commit_group;");
}
template <int N>
__device__ __forceinline__ void cp_wait() {
    asm volatile("cp.async.wait_group %0;" :: "n"(N));
}

// ---- MMA on one K=16 chunk. B fragments always raw bits (HW truncates to tf32).
// A fragments: CVTA ? cvt.rna : raw bits (for pre-rounded intermediates).

// A stored k-major: As[k][m], row stride AST (mod 32 == 8 for no conflicts)
template <int MT, int NT, int AST, int BST, bool CVTA>
__device__ __forceinline__ void mma_akm(const float* __restrict__ As,
                                        const float* __restrict__ Bs,
                                        int mbase, int nbase, float (*acc)[NT][4]) {
    int lane = threadIdx.x & 31;
    int g = lane >> 2, tg = lane & 3;
#pragma unroll
    for (int ks = 0; ks < 2; ks++) {
        uint32_t a[MT][4], b[NT][2];
#pragma unroll
        for (int i = 0; i < MT; i++) {
            const float* p = As + (ks * 8 + tg) * AST + mbase + i * 16 + g;
            if (CVTA) {
                a[i][0] = f2tf32(p[0]);
                a[i][1] = f2tf32(p[8]);
                a[i][2] = f2tf32(p[4 * AST]);
                a[i][3] = f2tf32(p[4 * AST + 8]);
            } else {
                a[i][0] = __float_as_uint(p[0]);
                a[i][1] = __float_as_uint(p[8]);
                a[i][2] = __float_as_uint(p[4 * AST]);
                a[i][3] = __float_as_uint(p[4 * AST + 8]);
            }
        }
#pragma unroll
        for (int j = 0; j < NT; j++) {
            const uint32_t* p = (const uint32_t*)Bs + (ks * 8 + tg) * BST + nbase + j * 8 + g;
            b[j][0] = p[0];
            b[j][1] = p[4 * BST];
        }
#pragma unroll
        for (int i = 0; i < MT; i++)
#pragma unroll
            for (int j = 0; j < NT; j++)
                asm volatile(
                    "mma.sync.aligned.m16n8k8.row.col.f32.tf32.tf32.f32 "
                    "{%0,%1,%2,%3},{%4,%5,%6,%7},{%8,%9},{%0,%1,%2,%3};\n"
                    : "+f"(acc[i][j][0]), "+f"(acc[i][j][1]),
                      "+f"(acc[i][j][2]), "+f"(acc[i][j][3])
                    : "r"(a[i][0]), "r"(a[i][1]), "r"(a[i][2]), "r"(a[i][3]),
                      "r"(b[j][0]), "r"(b[j][1]));
    }
}

// A stored m-major: As[m][k], row stride AST=20 (g*20+tg distinct mod 32)
template <int MT, int NT, int AST, int BST, bool CVTA>
__device__ __forceinline__ void mma_amk(const float* __restrict__ As,
                                        const float* __restrict__ Bs,
                                        int mbase, int nbase, float (*acc)[NT][4]) {
    int lane = threadIdx.x & 31;
    int g = lane >> 2, tg = lane & 3;
#pragma unroll
    for (int ks = 0; ks < 2; ks++) {
        uint32_t a[MT][4], b[NT][2];
#pragma unroll
        for (int i = 0; i < MT; i++) {
            const float* p = As + (size_t)(mbase + i * 16 + g) * AST + ks * 8 + tg;
            if (CVTA) {
                a[i][0] = f2tf32(p[0]);
                a[i][1] = f2tf32(p[8 * AST]);
                a[i][2] = f2tf32(p[4]);
                a[i][3] = f2tf32(p[8 * AST + 4]);
            } else {
                a[i][0] = __float_as_uint(p[0]);
                a[i][1] = __float_as_uint(p[8 * AST]);
                a[i][2] = __float_as_uint(p[4]);
                a[i][3] = __float_as_uint(p[8 * AST + 4]);
            }
        }
#pragma unroll
        for (int j = 0; j < NT; j++) {
            const uint32_t* p = (const uint32_t*)Bs + (ks * 8 + tg) * BST + nbase + j * 8 + g;
            b[j][0] = p[0];
            b[j][1] = p[4 * BST];
        }
#pragma unroll
        for (int i = 0; i < MT; i++)
#pragma unroll
            for (int j = 0; j < NT; j++)
                asm volatile(
                    "mma.sync.aligned.m16n8k8.row.col.f32.tf32.tf32.f32 "
                    "{%0,%1,%2,%3},{%4,%5,%6,%7},{%8,%9},{%0,%1,%2,%3};\n"
                    : "+f"(acc[i][j][0]), "+f"(acc[i][j][1]),
                      "+f"(acc[i][j][2]), "+f"(acc[i][j][3])
                    : "r"(a[i][0]), "r"(a[i][1]), "r"(a[i][2]), "r"(a[i][3]),
                      "r"(b[j][0]), "r"(b[j][1]));
    }
}

// ============ 1) logits + fused combine-softmax ============================
// rows r = b*M+m. BM=64, BN=128 (all slots). block 256 (warps 2x4, MT=2 NT=4).
// 3-stage cp.async. Epilogue: write raw logits + row-softmax -> g_combine.
#define LG_A (64 * 20)
#define LG_B (16 * 136)
__global__ void __launch_bounds__(256) logits_mma(const float* __restrict__ x,
                                                  const float* __restrict__ phi) {
    const int r0 = blockIdx.x * 64;
    __shared__ float Sbuf[3 * LG_A + 3 * LG_B];
    float* As = Sbuf;            // [3][64*20]
    float* Bs = Sbuf + 3 * LG_A; // [3][16*136]

    int tid = threadIdx.x, warp = tid >> 5, lane = tid & 31;
    int mbase = (warp >> 2) * 32, nbase = (warp & 3) * 32;
    float acc[2][4][4] = {};

    const float* xb = x + (size_t)r0 * Dq;
    const int NC = Dq / 16;  // 64

    auto issue = [&](int c) {
        int k0 = c * 16, st = c % 3;
        {
            int row = tid >> 2, kc = (tid & 3) * 4;
            cp16(smem_u32(&As[st * LG_A + row * 20 + kc]), &xb[(size_t)row * Dq + k0 + kc]);
        }
#pragma unroll
        for (int u = 0; u < 2; u++) {
            int idx = tid + u * 256;
            int kk = idx >> 5, sc = (idx & 31) * 4;
            cp16(smem_u32(&Bs[st * LG_B + kk * 136 + sc]), &phi[(size_t)(k0 + kk) * Sq + sc]);
        }
        cp_commit();
    };
    issue(0); issue(1);
#pragma unroll 1
    for (int c = 0; c < NC; c++) {
        cp_wait<1>();
        __syncthreads();
        if (c + 2 < NC) issue(c + 2); else cp_commit();
        mma_amk<2, 4, 20, 136, true>(&As[(c % 3) * LG_A], &Bs[(c % 3) * LG_B],
                                     mbase, nbase, acc);
        __syncthreads();
    }

    // epilogue: stash logits in smem overlay + write raw logits to global
    float (*L)[132] = (float(*)[132])Sbuf;  // 64*132 = 8448 floats <= 10368
    int g = lane >> 2, tg = lane & 3;
    float* lb = g_logits + (size_t)r0 * Sq;
    __syncthreads();
#pragma unroll
    for (int i = 0; i < 2; i++)
#pragma unroll
        for (int j = 0; j < 4; j++) {
            int row = mbase + i * 16 + g, col = nbase + j * 8 + tg * 2;
            float2 lo = make_float2(acc[i][j][0], acc[i][j][1]);
            float2 hi = make_float2(acc[i][j][2], acc[i][j][3]);
            *(float2*)&L[row][col] = lo;
            *(float2*)&L[row + 8][col] = hi;
            *(float2*)&lb[(size_t)row * Sq + col] = lo;
            *(float2*)&lb[(size_t)(row + 8) * Sq + col] = hi;
        }
    __syncthreads();

    // row softmax over S=128: each warp handles 8 rows
#pragma unroll 1
    for (int q = 0; q < 8; q++) {
        int row = warp * 8 + q;
        float v[4];
        float mx = -1e30f;
#pragma unroll
        for (int j = 0; j < 4; j++) {
            v[j] = L[row][lane + j * 32];
            mx = fmaxf(mx, v[j]);
        }
#pragma unroll
        for (int off = 16; off > 0; off >>= 1)
            mx = fmaxf(mx, __shfl_xor_sync(0xffffffffu, mx, off));
        float e[4], sum = 0.f;
#pragma unroll
        for (int j = 0; j < 4; j++) {
            e[j] = expf(v[j] - mx);
            sum += e[j];
        }
#pragma unroll
        for (int off = 16; off > 0; off >>= 1)
            sum += __shfl_xor_sync(0xffffffffu, sum, off);
        float inv = 1.f / sum;
        float* cp = g_combine + (size_t)(r0 + row) * Sq;
#pragma unroll
        for (int j = 0; j < 4; j++) cp[lane + j * 32] = round_tf32(e[j] * inv);
    }
}

// ============ 2) dispatch = softmax over M per (b,s), tf32-rounded =========
__global__ void dispatch_kernel() {
    int b = blockIdx.y;
    int s = blockIdx.x * 32 + threadIdx.x;
    int tx = threadIdx.x, ty = threadIdx.y;

    __shared__ float red[32][33];

    const float* lp = g_logits + (size_t)b * Mq * Sq + s;

    float mx = -1e30f;
    for (int m = ty; m < Mq; m += 32) mx = fmaxf(mx, lp[(size_t)m * Sq]);
    red[ty][tx] = mx;
    __syncthreads();
    for (int off = 16; off > 0; off >>= 1) {
        if (ty < off) red[ty][tx] = fmaxf(red[ty][tx], red[ty + off][tx]);
        __syncthreads();
    }
    mx = red[0][tx];
    __syncthreads();

    float sum = 0.f;
    for (int m = ty; m < Mq; m += 32) sum += expf(lp[(size_t)m * Sq] - mx);
    red[ty][tx] = sum;
    __syncthreads();
    for (int off = 16; off > 0; off >>= 1) {
        if (ty < off) red[ty][tx] += red[ty + off][tx];
        __syncthreads();
    }
    float inv = 1.f / red[0][tx];

    float* dp = g_dispatch + (size_t)b * Mq * Sq + s;
    for (int m = ty; m < Mq; m += 32)
        dp[(size_t)m * Sq] = round_tf32(expf(lp[(size_t)m * Sq] - mx) * inv);
}

// ============ 3) xs partials, split-K over M ===============================
// BM=64(s) BN=128(d), block 256 (warps 2x4, MT=2 NT=4). 3-stage. grid (8,2,B*KV).
__global__ void __launch_bounds__(256) xs_mma(const float* __restrict__ x) {
    const int b = blockIdx.z >> 2;
    const int kv = blockIdx.z & 3;
    const int s0 = blockIdx.y * 64;
    const int d0 = blockIdx.x * 128;
    const int mk = kv * (Mq / KV);
    __shared__ float As[3][16 * 72];
    __shared__ float Bs[3][16 * 136];

    int tid = threadIdx.x, warp = tid >> 5, lane = tid & 31;
    int mbase = (warp >> 2) * 32, nbase = (warp & 3) * 32;
    float acc[2][4][4] = {};

    const int NC = (Mq / KV) / 16;  // 32

    auto issue = [&](int c) {
        int k0 = mk + c * 16, st = c % 3;
        {
            int kk = tid >> 4, sc = (tid & 15) * 4;
            cp16(smem_u32(&As[st][kk * 72 + sc]),
                 &g_dispatch[((size_t)b * Mq + k0 + kk) * Sq + s0 + sc]);
        }
#pragma unroll
        for (int u = 0; u < 2; u++) {
            int idx = tid + u * 256;
            int kk = idx >> 5, dc = (idx & 31) * 4;
            cp16(smem_u32(&Bs[st][kk * 136 + dc]),
                 &x[((size_t)b * Mq + k0 + kk) * Dq + d0 + dc]);
        }
        cp_commit();
    };
    issue(0); issue(1);
#pragma unroll 1
    for (int c = 0; c < NC; c++) {
        cp_wait<1>();
        __syncthreads();
        if (c + 2 < NC) issue(c + 2); else cp_commit();
        mma_akm<2, 4, 72, 136, false>(As[c % 3], Bs[c % 3], mbase, nbase, acc);
    }

    int g = lane >> 2, tg = lane & 3;
    float* pp = g_xs_part + ((size_t)kv * Bq + b) * Sq * Dq;
#pragma unroll
    for (int i = 0; i < 2; i++)
#pragma unroll
        for (int j = 0; j < 4; j++) {
            int row = s0 + mbase + i * 16 + g, col = d0 + nbase + j * 8 + tg * 2;
            *(float2*)&pp[(size_t)row * Dq + col] = make_float2(acc[i][j][0], acc[i][j][1]);
            *(float2*)&pp[(size_t)(row + 8) * Dq + col] = make_float2(acc[i][j][2], acc[i][j][3]);
        }
}

// ============ 3b) xs = sum_kv partials (tf32-rounded) ======================
__global__ void __launch_bounds__(256) xs_reduce() {
    int i = blockIdx.x * 256 + threadIdx.x;  // float4 index
    const int stride = Bq * Sq * Dq / 4;
    const float4* p = (const float4*)g_xs_part;
    float4 a = p[i];
    float4 b = p[i + stride];
    float4 c = p[i + 2 * stride];
    float4 d = p[i + 3 * stride];
    ((float4*)g_xs)[i] = make_float4(round_tf32(a.x + b.x + c.x + d.x),
                                     round_tf32(a.y + b.y + c.y + d.y),
                                     round_tf32(a.z + b.z + c.z + d.z),
                                     round_tf32(a.w + b.w + c.w + d.w));
}

// ============ 4a) h = relu(xs @ w1 + b1)^2 per expert ======================
// BM=32 BN=128, block 128 (warps 1x4, MT=2 NT=4). 4-stage. grid (16, 32).
__global__ void __launch_bounds__(128) ffn1_mma(const float* __restrict__ w1,
                                                const float* __restrict__ b1) {
    const int n = blockIdx.y;
    const int f0 = blockIdx.x * 128;
    __shared__ float As[4][32 * 20];
    __shared__ float Bs[4][16 * 136];

    int tid = threadIdx.x, warp = tid >> 5, lane = tid & 31;
    int nbase = warp * 32;
    float acc[2][4][4] = {};

    const int NC = Dq / 16;  // 64

    auto issue = [&](int c) {
        int k0 = c * 16, st = c & 3;
        {
            int row = tid >> 2, kc = (tid & 3) * 4;
            cp16(smem_u32(&As[st][row * 20 + kc]),
                 &g_xs[(((size_t)(row >> 2)) * Sq + n * 4 + (row & 3)) * Dq + k0 + kc]);
        }
#pragma unroll
        for (int u = 0; u < 4; u++) {
            int idx = tid + u * 128;
            int kk = idx >> 5, fc = (idx & 31) * 4;
            cp16(smem_u32(&Bs[st][kk * 136 + fc]),
                 &w1[((size_t)n * Dq + k0 + kk) * Fq + f0 + fc]);
        }
        cp_commit();
    };
    issue(0); issue(1); issue(2);
#pragma unroll 1
    for (int c = 0; c < NC; c++) {
        cp_wait<2>();
        __syncthreads();
        if (c + 3 < NC) issue(c + 3); else cp_commit();
        mma_amk<2, 4, 20, 136, false>(As[c & 3], Bs[c & 3], 0, nbase, acc);
    }

    int g = lane >> 2, tg = lane & 3;
#pragma unroll
    for (int i = 0; i < 2; i++)
#pragma unroll
        for (int j = 0; j < 4; j++) {
            int row = i * 16 + g;
            int col = nbase + j * 8 + tg * 2;
#pragma unroll
            for (int half = 0; half < 2; half++) {
                int rr = row + half * 8;
                float h0 = acc[i][j][half * 2 + 0] + b1[(size_t)n * Fq + f0 + col];
                float h1 = acc[i][j][half * 2 + 1] + b1[(size_t)n * Fq + f0 + col + 1];
                h0 = fmaxf(h0, 0.f); h1 = fmaxf(h1, 0.f);
                float* hp = &g_h[(((size_t)(rr >> 2)) * Sq + n * 4 + (rr & 3)) * Fq + f0 + col];
                *(float2*)hp = make_float2(round_tf32(h0 * h0), round_tf32(h1 * h1));
            }
        }
}

// ============ 4b) y = h @ w2 + b2 per expert ===============================
// BM=32 BN=128, block 128 (warps 1x4, MT=2 NT=4). 4-stage. grid (8, 32).
__global__ void __launch_bounds__(128) ffn2_mma(const float* __restrict__ w2,
                                                const float* __restrict__ b2) {
    const int n = blockIdx.y;
    const int d0 = blockIdx.x * 128;
    __shared__ float As[4][32 * 20];
    __shared__ float Bs[4][16 * 136];

    int tid = threadIdx.x, warp = tid >> 5, lane = tid & 31;
    int nbase = warp * 32;
    float acc[2][4][4] = {};

    const int NC = Fq / 16;  // 128

    auto issue = [&](int c) {
        int k0 = c * 16, st = c & 3;
        {
            int row = tid >> 2, kc = (tid & 3) * 4;
            cp16(smem_u32(&As[st][row * 20 + kc]),
                 &g_h[(((size_t)(row >> 2)) * Sq + n * 4 + (row & 3)) * Fq + k0 + kc]);
        }
#pragma unroll
        for (int u = 0; u < 4; u++) {
            int idx = tid + u * 128;
            int kk = idx >> 5, dc = (idx & 31) * 4;
            cp16(smem_u32(&Bs[st][kk * 136 + dc]),
                 &w2[((size_t)n * Fq + k0 + kk) * Dq + d0 + dc]);
        }
        cp_commit();
    };
    issue(0); issue(1); issue(2);
#pragma unroll 1
    for (int c = 0; c < NC; c++) {
        cp_wait<2>();
        __syncthreads();
        if (c + 3 < NC) issue(c + 3); else cp_commit();
        mma_amk<2, 4, 20, 136, false>(As[c & 3], Bs[c & 3], 0, nbase, acc);
    }

    int g = lane >> 2, tg = lane & 3;
#pragma unroll
    for (int i = 0; i < 2; i++)
#pragma unroll
        for (int j = 0; j < 4; j++) {
            int row = i * 16 + g;
            int col = nbase + j * 8 + tg * 2;
#pragma unroll
            for (int half = 0; half < 2; half++) {
                int rr = row + half * 8;
                float y0 = acc[i][j][half * 2 + 0] + b2[(size_t)n * Dq + d0 + col];
                float y1 = acc[i][j][half * 2 + 1] + b2[(size_t)n * Dq + d0 + col + 1];
                float* yp = &g_y[(((size_t)(rr >> 2)) * Sq + n * 4 + (rr & 3)) * Dq + d0 + col];
                *(float2*)yp = make_float2(y0, y1);
            }
        }
}

// ============ 5) out[b,m,d] = sum_s combine[b,m,s] * y[b,s,d] ==============
// BM=128 BN=128, block 256 (warps 2x4, MT=4 NT=4). 2-stage. grid (8,16,8). K=128.
__global__ void __launch_bounds__(256) out_mma(float* __restrict__ out) {
    const int b = blockIdx.z;
    const int m0 = blockIdx.y * 128;
    const int d0 = blockIdx.x * 128;
    __shared__ float As[2][128 * 20];
    __shared__ float Bs[2][16 * 136];

    int tid = threadIdx.x, warp = tid >> 5, lane = tid & 31;
    int mbase = (warp >> 2) * 64, nbase = (warp & 3) * 32;
    float acc[4][4][4] = {};

    const float* cb = g_combine + ((size_t)b * Mq + m0) * Sq;
    const int NC = Sq / 16;  // 8

    auto issue = [&](int c) {
        int k0 = c * 16, st = c & 1;
#pragma unroll
        for (int u = 0; u < 2; u++) {
            int idx = tid + u * 256;
            int row = idx >> 2, kc = (idx & 3) * 4;
            cp16(smem_u32(&As[st][row * 20 + kc]), &cb[(size_t)row * Sq + k0 + kc]);
            int kk = idx >> 5, dc = (idx & 31) * 4;
            cp16(smem_u32(&Bs[st][kk * 136 + dc]),
                 &g_y[((size_t)b * Sq + k0 + kk) * Dq + d0 + dc]);
        }
        cp_commit();
    };
    issue(0);
#pragma unroll 1
    for (int c = 0; c < NC; c++) {
        cp_wait<0>();
        __syncthreads();
        if (c + 1 < NC) issue(c + 1);
        mma_amk<4, 4, 20, 136, false>(As[c & 1], Bs[c & 1], mbase, nbase, acc);
        __syncthreads();
    }

    int g = lane >> 2, tg = lane & 3;
    float* ob = out + ((size_t)b * Mq + m0) * Dq + d0;
#pragma unroll
    for (int i = 0; i < 4; i++)
#pragma unroll
        for (int j = 0; j < 4; j++) {
            int row = mbase + i * 16 + g, col = nbase + j * 8 + tg * 2;
            *(float2*)&ob[(size_t)row * Dq + col] = make_float2(acc[i][j][0], acc[i][j][1]);
            *(float2*)&ob[(size_t)(row + 8) * Dq + col] = make_float2(acc[i][j][2], acc[i][j][3]);
        }
}

// ---------------------------------------------------------------------------
extern "C" void kernel_launch(void* const* d_in, const int* in_sizes, int n_in,
                              void* d_out, int out_size) {
    const float* x   = (const float*)d_in[0];
    const float* phi = (const float*)d_in[1];
    const float* w1  = (const float*)d_in[2];
    const float* b1  = (const float*)d_in[3];
    const float* w2  = (const float*)d_in[4];
    const float* b2  = (const float*)d_in[5];
    float* out = (float*)d_out;

    logits_mma<<<(Bq * Mq) / 64, 256>>>(x, phi);
    dispatch_kernel<<<dim3(Sq / 32, Bq), dim3(32, 32)>>>();
    xs_mma<<<dim3(Dq / 128, Sq / 64, Bq * KV), 256>>>(x);
    xs_reduce<<<(Bq * Sq * Dq / 4) / 256, 256>>>();
    ffn1_mma<<<dim3(Fq / 128, Nq), 128>>>(w1, b1);
    ffn2_mma<<<dim3(Dq / 128, Nq), 128>>>(w2, b2);
    out_mma<<<dim3(Dq / 128, Mq / 128, Bq), 256>>>(out);
}

// round 6
// speedup vs baseline: 6.2233x; 1.0458x over previous
#include <cuda_runtime.h>
#include <math.h>
#include <stdint.h>

#define Bq 8
#define Mq 2048
#define Dq 1024
#define Fq 2048
#define Nq 32
#define Pq 4
#define Sq 128   // N*P slots
#define KV 4     // split-K factor for xs stage
#define MSP 4    // M-split for dispatch softmax

// ---------------- scratch (device globals; no allocation allowed) ----------
__device__ float g_logits[Bq * Mq * Sq];        // 8 MB   (B,M,S)
__device__ float g_dispatch[Bq * Mq * Sq];      // 8 MB   (B,M,S)  tf32-rounded
__device__ float g_combine[Bq * Mq * Sq];       // 8 MB   (B,M,S)  tf32-rounded
__device__ float g_xs[Bq * Sq * Dq];            // 4 MB   (B,S,D)  tf32-rounded
__device__ float g_xs_part[KV * Bq * Sq * Dq];  // 16 MB  (KV,B,S,D)
__device__ float g_h[Bq * Sq * Fq];             // 8 MB   (B,S,F)  tf32-rounded
__device__ float g_y[Bq * Sq * Dq];             // 4 MB   (B,S,D)
__device__ float g_dmx[MSP * Bq * Sq];          // partial max
__device__ float g_dsum[MSP * Bq * Sq];         // partial sum

// float -> tf32 (round-to-nearest) kept in a 32-bit register
__device__ __forceinline__ uint32_t f2tf32(float f) {
    uint32_t r;
    asm("cvt.rna.tf32.f32 %0, %1;" : "=r"(r) : "f"(f));
    return r;
}
__device__ __forceinline__ float round_tf32(float f) {
    return __uint_as_float(f2tf32(f));
}

__device__ __forceinline__ uint32_t smem_u32(const void* p) {
    return (uint32_t)__cvta_generic_to_shared(p);
}
__device__ __forceinline__ void cp16(uint32_t dst, const void* src) {
    asm volatile("cp.async.cg.shared.global [%0], [%1], 16;" :: "r"(dst), "l"(src));
}
__device__ __forceinline__ void cp_commit() {
    asm volatile("cp.async.commit_group;");
}
template <int N>
__device__ __forceinline__ void cp_wait() {
    asm volatile("cp.async.wait_group %0;" :: "n"(N));
}

// ---- MMA on one K=16 chunk. B fragments always raw bits (HW truncates to tf32).
// A fragments: CVTA ? cvt.rna : raw bits (for pre-rounded intermediates).

// A stored k-major: As[k][m], row stride AST (mod 32 == 8 for no conflicts)
template <int MT, int NT, int AST, int BST, bool CVTA>
__device__ __forceinline__ void mma_akm(const float* __restrict__ As,
                                        const float* __restrict__ Bs,
                                        int mbase, int nbase, float (*acc)[NT][4]) {
    int lane = threadIdx.x & 31;
    int g = lane >> 2, tg = lane & 3;
#pragma unroll
    for (int ks = 0; ks < 2; ks++) {
        uint32_t a[MT][4], b[NT][2];
#pragma unroll
        for (int i = 0; i < MT; i++) {
            const float* p = As + (ks * 8 + tg) * AST + mbase + i * 16 + g;
            if (CVTA) {
                a[i][0] = f2tf32(p[0]);
                a[i][1] = f2tf32(p[8]);
                a[i][2] = f2tf32(p[4 * AST]);
                a[i][3] = f2tf32(p[4 * AST + 8]);
            } else {
                a[i][0] = __float_as_uint(p[0]);
                a[i][1] = __float_as_uint(p[8]);
                a[i][2] = __float_as_uint(p[4 * AST]);
                a[i][3] = __float_as_uint(p[4 * AST + 8]);
            }
        }
#pragma unroll
        for (int j = 0; j < NT; j++) {
            const uint32_t* p = (const uint32_t*)Bs + (ks * 8 + tg) * BST + nbase + j * 8 + g;
            b[j][0] = p[0];
            b[j][1] = p[4 * BST];
        }
#pragma unroll
        for (int i = 0; i < MT; i++)
#pragma unroll
            for (int j = 0; j < NT; j++)
                asm volatile(
                    "mma.sync.aligned.m16n8k8.row.col.f32.tf32.tf32.f32 "
                    "{%0,%1,%2,%3},{%4,%5,%6,%7},{%8,%9},{%0,%1,%2,%3};\n"
                    : "+f"(acc[i][j][0]), "+f"(acc[i][j][1]),
                      "+f"(acc[i][j][2]), "+f"(acc[i][j][3])
                    : "r"(a[i][0]), "r"(a[i][1]), "r"(a[i][2]), "r"(a[i][3]),
                      "r"(b[j][0]), "r"(b[j][1]));
    }
}

// A stored m-major: As[m][k], row stride AST=20 (g*20+tg distinct mod 32)
template <int MT, int NT, int AST, int BST, bool CVTA>
__device__ __forceinline__ void mma_amk(const float* __restrict__ As,
                                        const float* __restrict__ Bs,
                                        int mbase, int nbase, float (*acc)[NT][4]) {
    int lane = threadIdx.x & 31;
    int g = lane >> 2, tg = lane & 3;
#pragma unroll
    for (int ks = 0; ks < 2; ks++) {
        uint32_t a[MT][4], b[NT][2];
#pragma unroll
        for (int i = 0; i < MT; i++) {
            const float* p = As + (size_t)(mbase + i * 16 + g) * AST + ks * 8 + tg;
            if (CVTA) {
                a[i][0] = f2tf32(p[0]);
                a[i][1] = f2tf32(p[8 * AST]);
                a[i][2] = f2tf32(p[4]);
                a[i][3] = f2tf32(p[8 * AST + 4]);
            } else {
                a[i][0] = __float_as_uint(p[0]);
                a[i][1] = __float_as_uint(p[8 * AST]);
                a[i][2] = __float_as_uint(p[4]);
                a[i][3] = __float_as_uint(p[8 * AST + 4]);
            }
        }
#pragma unroll
        for (int j = 0; j < NT; j++) {
            const uint32_t* p = (const uint32_t*)Bs + (ks * 8 + tg) * BST + nbase + j * 8 + g;
            b[j][0] = p[0];
            b[j][1] = p[4 * BST];
        }
#pragma unroll
        for (int i = 0; i < MT; i++)
#pragma unroll
            for (int j = 0; j < NT; j++)
                asm volatile(
                    "mma.sync.aligned.m16n8k8.row.col.f32.tf32.tf32.f32 "
                    "{%0,%1,%2,%3},{%4,%5,%6,%7},{%8,%9},{%0,%1,%2,%3};\n"
                    : "+f"(acc[i][j][0]), "+f"(acc[i][j][1]),
                      "+f"(acc[i][j][2]), "+f"(acc[i][j][3])
                    : "r"(a[i][0]), "r"(a[i][1]), "r"(a[i][2]), "r"(a[i][3]),
                      "r"(b[j][0]), "r"(b[j][1]));
    }
}

// ============ 1) logits + fused combine-softmax ============================
// rows r = b*M+m. BM=64, BN=128 (all slots). block 256 (warps 2x4, MT=2 NT=4).
// 3-stage cp.async, single sync per chunk.
#define LG_A (64 * 20)
#define LG_B (16 * 136)
__global__ void __launch_bounds__(256) logits_mma(const float* __restrict__ x,
                                                  const float* __restrict__ phi) {
    const int r0 = blockIdx.x * 64;
    __shared__ float Sbuf[3 * LG_A + 3 * LG_B];
    float* As = Sbuf;            // [3][64*20]
    float* Bs = Sbuf + 3 * LG_A; // [3][16*136]

    int tid = threadIdx.x, warp = tid >> 5, lane = tid & 31;
    int mbase = (warp >> 2) * 32, nbase = (warp & 3) * 32;
    float acc[2][4][4] = {};

    const float* xb = x + (size_t)r0 * Dq;
    const int NC = Dq / 16;  // 64

    auto issue = [&](int c) {
        int k0 = c * 16, st = c % 3;
        {
            int row = tid >> 2, kc = (tid & 3) * 4;
            cp16(smem_u32(&As[st * LG_A + row * 20 + kc]), &xb[(size_t)row * Dq + k0 + kc]);
        }
#pragma unroll
        for (int u = 0; u < 2; u++) {
            int idx = tid + u * 256;
            int kk = idx >> 5, sc = (idx & 31) * 4;
            cp16(smem_u32(&Bs[st * LG_B + kk * 136 + sc]), &phi[(size_t)(k0 + kk) * Sq + sc]);
        }
        cp_commit();
    };
    issue(0); issue(1);
#pragma unroll 1
    for (int c = 0; c < NC; c++) {
        cp_wait<1>();
        __syncthreads();
        if (c + 2 < NC) issue(c + 2); else cp_commit();
        mma_amk<2, 4, 20, 136, true>(&As[(c % 3) * LG_A], &Bs[(c % 3) * LG_B],
                                     mbase, nbase, acc);
    }

    // epilogue: stash logits in smem overlay + write raw logits to global
    float (*L)[132] = (float(*)[132])Sbuf;  // 64*132 = 8448 floats <= 10368
    int g = lane >> 2, tg = lane & 3;
    float* lb = g_logits + (size_t)r0 * Sq;
    __syncthreads();
#pragma unroll
    for (int i = 0; i < 2; i++)
#pragma unroll
        for (int j = 0; j < 4; j++) {
            int row = mbase + i * 16 + g, col = nbase + j * 8 + tg * 2;
            float2 lo = make_float2(acc[i][j][0], acc[i][j][1]);
            float2 hi = make_float2(acc[i][j][2], acc[i][j][3]);
            *(float2*)&L[row][col] = lo;
            *(float2*)&L[row + 8][col] = hi;
            *(float2*)&lb[(size_t)row * Sq + col] = lo;
            *(float2*)&lb[(size_t)(row + 8) * Sq + col] = hi;
        }
    __syncthreads();

    // row softmax over S=128: each warp handles 8 rows
#pragma unroll 1
    for (int q = 0; q < 8; q++) {
        int row = warp * 8 + q;
        float v[4];
        float mx = -1e30f;
#pragma unroll
        for (int j = 0; j < 4; j++) {
            v[j] = L[row][lane + j * 32];
            mx = fmaxf(mx, v[j]);
        }
#pragma unroll
        for (int off = 16; off > 0; off >>= 1)
            mx = fmaxf(mx, __shfl_xor_sync(0xffffffffu, mx, off));
        float e[4], sum = 0.f;
#pragma unroll
        for (int j = 0; j < 4; j++) {
            e[j] = expf(v[j] - mx);
            sum += e[j];
        }
#pragma unroll
        for (int off = 16; off > 0; off >>= 1)
            sum += __shfl_xor_sync(0xffffffffu, sum, off);
        float inv = 1.f / sum;
        float* cp = g_combine + (size_t)(r0 + row) * Sq;
#pragma unroll
        for (int j = 0; j < 4; j++) cp[lane + j * 32] = round_tf32(e[j] * inv);
    }
}

// ============ 2a) dispatch partials: (max, sum) over M-chunk per (b,s) =====
// grid (Sq/32, Bq, MSP), block (32, 32). 16 rows per thread, register-cached.
__global__ void dispatch_part() {
    int b = blockIdx.y, ch = blockIdx.z;
    int s = blockIdx.x * 32 + threadIdx.x;
    int tx = threadIdx.x, ty = threadIdx.y;
    const float* lp = g_logits + ((size_t)b * Mq + ch * (Mq / MSP)) * Sq + s;

    float v[16];
#pragma unroll
    for (int i = 0; i < 16; i++) v[i] = lp[(size_t)(ty + i * 32) * Sq];
    float mx = v[0];
#pragma unroll
    for (int i = 1; i < 16; i++) mx = fmaxf(mx, v[i]);
    float sum = 0.f;
#pragma unroll
    for (int i = 0; i < 16; i++) sum += expf(v[i] - mx);

    __shared__ float rm[32][33], rs[32][33];
    rm[ty][tx] = mx;
    rs[ty][tx] = sum;
    __syncthreads();
    for (int off = 16; off > 0; off >>= 1) {
        if (ty < off) {
            float m1 = rm[ty][tx], s1 = rs[ty][tx];
            float m2 = rm[ty + off][tx], s2 = rs[ty + off][tx];
            float m = fmaxf(m1, m2);
            rm[ty][tx] = m;
            rs[ty][tx] = s1 * expf(m1 - m) + s2 * expf(m2 - m);
        }
        __syncthreads();
    }
    if (ty == 0) {
        g_dmx[(ch * Bq + b) * Sq + s] = rm[0][tx];
        g_dsum[(ch * Bq + b) * Sq + s] = rs[0][tx];
    }
}

// ============ 2b) dispatch write: combine partials + normalize =============
// grid (Sq/32, Bq, MSP), block (32, 32).
__global__ void dispatch_write() {
    int b = blockIdx.y, ch = blockIdx.z;
    int s = blockIdx.x * 32 + threadIdx.x;
    int ty = threadIdx.y;

    float mx = g_dmx[(0 * Bq + b) * Sq + s];
    float sum = g_dsum[(0 * Bq + b) * Sq + s];
#pragma unroll
    for (int c = 1; c < MSP; c++) {
        float m2 = g_dmx[(c * Bq + b) * Sq + s];
        float s2 = g_dsum[(c * Bq + b) * Sq + s];
        float m = fmaxf(mx, m2);
        sum = sum * expf(mx - m) + s2 * expf(m2 - m);
        mx = m;
    }
    float inv = 1.f / sum;

    const float* lp = g_logits + ((size_t)b * Mq + ch * (Mq / MSP)) * Sq + s;
    float* dp = g_dispatch + ((size_t)b * Mq + ch * (Mq / MSP)) * Sq + s;
#pragma unroll
    for (int i = 0; i < 16; i++) {
        size_t off = (size_t)(ty + i * 32) * Sq;
        dp[off] = round_tf32(expf(lp[off] - mx) * inv);
    }
}

// ============ 3) xs partials, split-K over M ===============================
// BM=64(s) BN=128(d), block 256 (warps 2x4, MT=2 NT=4). 3-stage. grid (8,2,B*KV).
__global__ void __launch_bounds__(256) xs_mma(const float* __restrict__ x) {
    const int b = blockIdx.z >> 2;
    const int kv = blockIdx.z & 3;
    const int s0 = blockIdx.y * 64;
    const int d0 = blockIdx.x * 128;
    const int mk = kv * (Mq / KV);
    __shared__ float As[3][16 * 72];
    __shared__ float Bs[3][16 * 136];

    int tid = threadIdx.x, warp = tid >> 5, lane = tid & 31;
    int mbase = (warp >> 2) * 32, nbase = (warp & 3) * 32;
    float acc[2][4][4] = {};

    const int NC = (Mq / KV) / 16;  // 32

    auto issue = [&](int c) {
        int k0 = mk + c * 16, st = c % 3;
        {
            int kk = tid >> 4, sc = (tid & 15) * 4;
            cp16(smem_u32(&As[st][kk * 72 + sc]),
                 &g_dispatch[((size_t)b * Mq + k0 + kk) * Sq + s0 + sc]);
        }
#pragma unroll
        for (int u = 0; u < 2; u++) {
            int idx = tid + u * 256;
            int kk = idx >> 5, dc = (idx & 31) * 4;
            cp16(smem_u32(&Bs[st][kk * 136 + dc]),
                 &x[((size_t)b * Mq + k0 + kk) * Dq + d0 + dc]);
        }
        cp_commit();
    };
    issue(0); issue(1);
#pragma unroll 1
    for (int c = 0; c < NC; c++) {
        cp_wait<1>();
        __syncthreads();
        if (c + 2 < NC) issue(c + 2); else cp_commit();
        mma_akm<2, 4, 72, 136, false>(As[c % 3], Bs[c % 3], mbase, nbase, acc);
    }

    int g = lane >> 2, tg = lane & 3;
    float* pp = g_xs_part + ((size_t)kv * Bq + b) * Sq * Dq;
#pragma unroll
    for (int i = 0; i < 2; i++)
#pragma unroll
        for (int j = 0; j < 4; j++) {
            int row = s0 + mbase + i * 16 + g, col = d0 + nbase + j * 8 + tg * 2;
            *(float2*)&pp[(size_t)row * Dq + col] = make_float2(acc[i][j][0], acc[i][j][1]);
            *(float2*)&pp[(size_t)(row + 8) * Dq + col] = make_float2(acc[i][j][2], acc[i][j][3]);
        }
}

// ============ 3b) xs = sum_kv partials (tf32-rounded) ======================
__global__ void __launch_bounds__(256) xs_reduce() {
    int i = blockIdx.x * 256 + threadIdx.x;  // float4 index
    const int stride = Bq * Sq * Dq / 4;
    const float4* p = (const float4*)g_xs_part;
    float4 a = p[i];
    float4 b = p[i + stride];
    float4 c = p[i + 2 * stride];
    float4 d = p[i + 3 * stride];
    ((float4*)g_xs)[i] = make_float4(round_tf32(a.x + b.x + c.x + d.x),
                                     round_tf32(a.y + b.y + c.y + d.y),
                                     round_tf32(a.z + b.z + c.z + d.z),
                                     round_tf32(a.w + b.w + c.w + d.w));
}

// ============ 4a) h = relu(xs @ w1 + b1)^2 per expert ======================
// BM=32 BN=128, block 128 (warps 1x4, MT=2 NT=4). 4-stage. grid (16, 32).
__global__ void __launch_bounds__(128) ffn1_mma(const float* __restrict__ w1,
                                                const float* __restrict__ b1) {
    const int n = blockIdx.y;
    const int f0 = blockIdx.x * 128;
    __shared__ float As[4][32 * 20];
    __shared__ float Bs[4][16 * 136];

    int tid = threadIdx.x, warp = tid >> 5, lane = tid & 31;
    int nbase = warp * 32;
    float acc[2][4][4] = {};

    const int NC = Dq / 16;  // 64

    auto issue = [&](int c) {
        int k0 = c * 16, st = c & 3;
        {
            int row = tid >> 2, kc = (tid & 3) * 4;
            cp16(smem_u32(&As[st][row * 20 + kc]),
                 &g_xs[(((size_t)(row >> 2)) * Sq + n * 4 + (row & 3)) * Dq + k0 + kc]);
        }
#pragma unroll
        for (int u = 0; u < 4; u++) {
            int idx = tid + u * 128;
            int kk = idx >> 5, fc = (idx & 31) * 4;
            cp16(smem_u32(&Bs[st][kk * 136 + fc]),
                 &w1[((size_t)n * Dq + k0 + kk) * Fq + f0 + fc]);
        }
        cp_commit();
    };
    issue(0); issue(1); issue(2);
#pragma unroll 1
    for (int c = 0; c < NC; c++) {
        cp_wait<2>();
        __syncthreads();
        if (c + 3 < NC) issue(c + 3); else cp_commit();
        mma_amk<2, 4, 20, 136, false>(As[c & 3], Bs[c & 3], 0, nbase, acc);
    }

    int g = lane >> 2, tg = lane & 3;
#pragma unroll
    for (int i = 0; i < 2; i++)
#pragma unroll
        for (int j = 0; j < 4; j++) {
            int row = i * 16 + g;
            int col = nbase + j * 8 + tg * 2;
#pragma unroll
            for (int half = 0; half < 2; half++) {
                int rr = row + half * 8;
                float h0 = acc[i][j][half * 2 + 0] + b1[(size_t)n * Fq + f0 + col];
                float h1 = acc[i][j][half * 2 + 1] + b1[(size_t)n * Fq + f0 + col + 1];
                h0 = fmaxf(h0, 0.f); h1 = fmaxf(h1, 0.f);
                float* hp = &g_h[(((size_t)(rr >> 2)) * Sq + n * 4 + (rr & 3)) * Fq + f0 + col];
                *(float2*)hp = make_float2(round_tf32(h0 * h0), round_tf32(h1 * h1));
            }
        }
}

// ============ 4b) y = h @ w2 + b2 per expert ===============================
// BM=32 BN=128, block 128 (warps 1x4, MT=2 NT=4). 4-stage. grid (8, 32).
__global__ void __launch_bounds__(128) ffn2_mma(const float* __restrict__ w2,
                                                const float* __restrict__ b2) {
    const int n = blockIdx.y;
    const int d0 = blockIdx.x * 128;
    __shared__ float As[4][32 * 20];
    __shared__ float Bs[4][16 * 136];

    int tid = threadIdx.x, warp = tid >> 5, lane = tid & 31;
    int nbase = warp * 32;
    float acc[2][4][4] = {};

    const int NC = Fq / 16;  // 128

    auto issue = [&](int c) {
        int k0 = c * 16, st = c & 3;
        {
            int row = tid >> 2, kc = (tid & 3) * 4;
            cp16(smem_u32(&As[st][row * 20 + kc]),
                 &g_h[(((size_t)(row >> 2)) * Sq + n * 4 + (row & 3)) * Fq + k0 + kc]);
        }
#pragma unroll
        for (int u = 0; u < 4; u++) {
            int idx = tid + u * 128;
            int kk = idx >> 5, dc = (idx & 31) * 4;
            cp16(smem_u32(&Bs[st][kk * 136 + dc]),
                 &w2[((size_t)n * Fq + k0 + kk) * Dq + d0 + dc]);
        }
        cp_commit();
    };
    issue(0); issue(1); issue(2);
#pragma unroll 1
    for (int c = 0; c < NC; c++) {
        cp_wait<2>();
        __syncthreads();
        if (c + 3 < NC) issue(c + 3); else cp_commit();
        mma_amk<2, 4, 20, 136, false>(As[c & 3], Bs[c & 3], 0, nbase, acc);
    }

    int g = lane >> 2, tg = lane & 3;
#pragma unroll
    for (int i = 0; i < 2; i++)
#pragma unroll
        for (int j = 0; j < 4; j++) {
            int row = i * 16 + g;
            int col = nbase + j * 8 + tg * 2;
#pragma unroll
            for (int half = 0; half < 2; half++) {
                int rr = row + half * 8;
                float y0 = acc[i][j][half * 2 + 0] + b2[(size_t)n * Dq + d0 + col];
                float y1 = acc[i][j][half * 2 + 1] + b2[(size_t)n * Dq + d0 + col + 1];
                float* yp = &g_y[(((size_t)(rr >> 2)) * Sq + n * 4 + (rr & 3)) * Dq + d0 + col];
                *(float2*)yp = make_float2(y0, y1);
            }
        }
}

// ============ 5) out[b,m,d] = sum_s combine[b,m,s] * y[b,s,d] ==============
// BM=64(m) BN=128(d), block 256 (warps 2x4, MT=2 NT=4). 3-stage, single sync.
// grid (8, 32, 8). K=S=128.
__global__ void __launch_bounds__(256) out_mma(float* __restrict__ out) {
    const int b = blockIdx.z;
    const int m0 = blockIdx.y * 64;
    const int d0 = blockIdx.x * 128;
    __shared__ float As[3][64 * 20];
    __shared__ float Bs[3][16 * 136];

    int tid = threadIdx.x, warp = tid >> 5, lane = tid & 31;
    int mbase = (warp >> 2) * 32, nbase = (warp & 3) * 32;
    float acc[2][4][4] = {};

    const float* cb = g_combine + ((size_t)b * Mq + m0) * Sq;
    const int NC = Sq / 16;  // 8

    auto issue = [&](int c) {
        int k0 = c * 16, st = c % 3;
        {
            int row = tid >> 2, kc = (tid & 3) * 4;
            cp16(smem_u32(&As[st][row * 20 + kc]), &cb[(size_t)row * Sq + k0 + kc]);
        }
#pragma unroll
        for (int u = 0; u < 2; u++) {
            int idx = tid + u * 256;
            int kk = idx >> 5, dc = (idx & 31) * 4;
            cp16(smem_u32(&Bs[st][kk * 136 + dc]),
                 &g_y[((size_t)b * Sq + k0 + kk) * Dq + d0 + dc]);
        }
        cp_commit();
    };
    issue(0); issue(1);
#pragma unroll 1
    for (int c = 0; c < NC; c++) {
        cp_wait<1>();
        __syncthreads();
        if (c + 2 < NC) issue(c + 2); else cp_commit();
        mma_amk<2, 4, 20, 136, false>(As[c % 3], Bs[c % 3], mbase, nbase, acc);
    }

    int g = lane >> 2, tg = lane & 3;
    float* ob = out + ((size_t)b * Mq + m0) * Dq + d0;
#pragma unroll
    for (int i = 0; i < 2; i++)
#pragma unroll
        for (int j = 0; j < 4; j++) {
            int row = mbase + i * 16 + g, col = nbase + j * 8 + tg * 2;
            *(float2*)&ob[(size_t)row * Dq + col] = make_float2(acc[i][j][0], acc[i][j][1]);
            *(float2*)&ob[(size_t)(row + 8) * Dq + col] = make_float2(acc[i][j][2], acc[i][j][3]);
        }
}

// ---------------------------------------------------------------------------
extern "C" void kernel_launch(void* const* d_in, const int* in_sizes, int n_in,
                              void* d_out, int out_size) {
    const float* x   = (const float*)d_in[0];
    const float* phi = (const float*)d_in[1];
    const float* w1  = (const float*)d_in[2];
    const float* b1  = (const float*)d_in[3];
    const float* w2  = (const float*)d_in[4];
    const float* b2  = (const float*)d_in[5];
    float* out = (float*)d_out;

    logits_mma<<<(Bq * Mq) / 64, 256>>>(x, phi);
    dispatch_part<<<dim3(Sq / 32, Bq, MSP), dim3(32, 32)>>>();
    dispatch_write<<<dim3(Sq / 32, Bq, MSP), dim3(32, 32)>>>();
    xs_mma<<<dim3(Dq / 128, Sq / 64, Bq * KV), 256>>>(x);
    xs_reduce<<<(Bq * Sq * Dq / 4) / 256, 256>>>();
    ffn1_mma<<<dim3(Fq / 128, Nq), 128>>>(w1, b1);
    ffn2_mma<<<dim3(Dq / 128, Nq), 128>>>(w2, b2);
    out_mma<<<dim3(Dq / 128, Mq / 64, Bq), 256>>>(out);
}

// round 7
// speedup vs baseline: 6.2258x; 1.0004x over previous
#include <cuda_runtime.h>
#include <math.h>
#include <stdint.h>

#define Bq 8
#define Mq 2048
#define Dq 1024
#define Fq 2048
#define Nq 32
#define Pq 4
#define Sq 128   // N*P slots
#define KV 8     // split-K factor for xs stage
#define MSP 4    // M-split for dispatch softmax

// ---------------- scratch (device globals; no allocation allowed) ----------
__device__ float g_logits[Bq * Mq * Sq];        // 8 MB   (B,M,S)
__device__ float g_dispatch[Bq * Mq * Sq];      // 8 MB   (B,M,S)  tf32-rounded
__device__ float g_combine[Bq * Mq * Sq];       // 8 MB   (B,M,S)  tf32-rounded
__device__ float g_xs[Bq * Sq * Dq];            // 4 MB   (B,S,D)  tf32-rounded
__device__ float g_xs_part[KV * Bq * Sq * Dq];  // 32 MB  (KV,B,S,D)
__device__ float g_h[Bq * Sq * Fq];             // 8 MB   (B,S,F)  tf32-rounded
__device__ float g_y[Bq * Sq * Dq];             // 4 MB   (B,S,D)
__device__ float g_dmx[MSP * Bq * Sq];          // partial max
__device__ float g_dsum[MSP * Bq * Sq];         // partial sum

// float -> tf32 (round-to-nearest) kept in a 32-bit register
__device__ __forceinline__ uint32_t f2tf32(float f) {
    uint32_t r;
    asm("cvt.rna.tf32.f32 %0, %1;" : "=r"(r) : "f"(f));
    return r;
}
__device__ __forceinline__ float round_tf32(float f) {
    return __uint_as_float(f2tf32(f));
}

__device__ __forceinline__ uint32_t smem_u32(const void* p) {
    return (uint32_t)__cvta_generic_to_shared(p);
}
__device__ __forceinline__ void cp16(uint32_t dst, const void* src) {
    asm volatile("cp.async.cg.shared.global [%0], [%1], 16;" :: "r"(dst), "l"(src));
}
__device__ __forceinline__ void cp_commit() {
    asm volatile("cp.async.commit_group;");
}
template <int N>
__device__ __forceinline__ void cp_wait() {
    asm volatile("cp.async.wait_group %0;" :: "n"(N));
}

// ---- MMA on one K=16 chunk. B fragments always raw bits (HW truncates to tf32).
// A fragments: CVTA ? cvt.rna : raw bits (for pre-rounded intermediates).

// A stored k-major: As[k][m], row stride AST (mod 32 == 8 for no conflicts)
template <int MT, int NT, int AST, int BST, bool CVTA>
__device__ __forceinline__ void mma_akm(const float* __restrict__ As,
                                        const float* __restrict__ Bs,
                                        int mbase, int nbase, float (*acc)[NT][4]) {
    int lane = threadIdx.x & 31;
    int g = lane >> 2, tg = lane & 3;
#pragma unroll
    for (int ks = 0; ks < 2; ks++) {
        uint32_t a[MT][4], b[NT][2];
#pragma unroll
        for (int i = 0; i < MT; i++) {
            const float* p = As + (ks * 8 + tg) * AST + mbase + i * 16 + g;
            if (CVTA) {
                a[i][0] = f2tf32(p[0]);
                a[i][1] = f2tf32(p[8]);
                a[i][2] = f2tf32(p[4 * AST]);
                a[i][3] = f2tf32(p[4 * AST + 8]);
            } else {
                a[i][0] = __float_as_uint(p[0]);
                a[i][1] = __float_as_uint(p[8]);
                a[i][2] = __float_as_uint(p[4 * AST]);
                a[i][3] = __float_as_uint(p[4 * AST + 8]);
            }
        }
#pragma unroll
        for (int j = 0; j < NT; j++) {
            const uint32_t* p = (const uint32_t*)Bs + (ks * 8 + tg) * BST + nbase + j * 8 + g;
            b[j][0] = p[0];
            b[j][1] = p[4 * BST];
        }
#pragma unroll
        for (int i = 0; i < MT; i++)
#pragma unroll
            for (int j = 0; j < NT; j++)
                asm volatile(
                    "mma.sync.aligned.m16n8k8.row.col.f32.tf32.tf32.f32 "
                    "{%0,%1,%2,%3},{%4,%5,%6,%7},{%8,%9},{%0,%1,%2,%3};\n"
                    : "+f"(acc[i][j][0]), "+f"(acc[i][j][1]),
                      "+f"(acc[i][j][2]), "+f"(acc[i][j][3])
                    : "r"(a[i][0]), "r"(a[i][1]), "r"(a[i][2]), "r"(a[i][3]),
                      "r"(b[j][0]), "r"(b[j][1]));
    }
}

// A stored m-major: As[m][k], row stride AST=20 (g*20+tg distinct mod 32)
template <int MT, int NT, int AST, int BST, bool CVTA>
__device__ __forceinline__ void mma_amk(const float* __restrict__ As,
                                        const float* __restrict__ Bs,
                                        int mbase, int nbase, float (*acc)[NT][4]) {
    int lane = threadIdx.x & 31;
    int g = lane >> 2, tg = lane & 3;
#pragma unroll
    for (int ks = 0; ks < 2; ks++) {
        uint32_t a[MT][4], b[NT][2];
#pragma unroll
        for (int i = 0; i < MT; i++) {
            const float* p = As + (size_t)(mbase + i * 16 + g) * AST + ks * 8 + tg;
            if (CVTA) {
                a[i][0] = f2tf32(p[0]);
                a[i][1] = f2tf32(p[8 * AST]);
                a[i][2] = f2tf32(p[4]);
                a[i][3] = f2tf32(p[8 * AST + 4]);
            } else {
                a[i][0] = __float_as_uint(p[0]);
                a[i][1] = __float_as_uint(p[8 * AST]);
                a[i][2] = __float_as_uint(p[4]);
                a[i][3] = __float_as_uint(p[8 * AST + 4]);
            }
        }
#pragma unroll
        for (int j = 0; j < NT; j++) {
            const uint32_t* p = (const uint32_t*)Bs + (ks * 8 + tg) * BST + nbase + j * 8 + g;
            b[j][0] = p[0];
            b[j][1] = p[4 * BST];
        }
#pragma unroll
        for (int i = 0; i < MT; i++)
#pragma unroll
            for (int j = 0; j < NT; j++)
                asm volatile(
                    "mma.sync.aligned.m16n8k8.row.col.f32.tf32.tf32.f32 "
                    "{%0,%1,%2,%3},{%4,%5,%6,%7},{%8,%9},{%0,%1,%2,%3};\n"
                    : "+f"(acc[i][j][0]), "+f"(acc[i][j][1]),
                      "+f"(acc[i][j][2]), "+f"(acc[i][j][3])
                    : "r"(a[i][0]), "r"(a[i][1]), "r"(a[i][2]), "r"(a[i][3]),
                      "r"(b[j][0]), "r"(b[j][1]));
    }
}

// ============ 1) logits + fused combine-softmax ============================
// rows r = b*M+m. BM=64, BN=128 (all slots). block 256 (warps 2x4, MT=2 NT=4).
// 3-stage cp.async, single sync per chunk.
#define LG_A (64 * 20)
#define LG_B (16 * 136)
__global__ void __launch_bounds__(256) logits_mma(const float* __restrict__ x,
                                                  const float* __restrict__ phi) {
    const int r0 = blockIdx.x * 64;
    __shared__ float Sbuf[3 * LG_A + 3 * LG_B];
    float* As = Sbuf;            // [3][64*20]
    float* Bs = Sbuf + 3 * LG_A; // [3][16*136]

    int tid = threadIdx.x, warp = tid >> 5, lane = tid & 31;
    int mbase = (warp >> 2) * 32, nbase = (warp & 3) * 32;
    float acc[2][4][4] = {};

    const float* xb = x + (size_t)r0 * Dq;
    const int NC = Dq / 16;  // 64

    auto issue = [&](int c) {
        int k0 = c * 16, st = c % 3;
        {
            int row = tid >> 2, kc = (tid & 3) * 4;
            cp16(smem_u32(&As[st * LG_A + row * 20 + kc]), &xb[(size_t)row * Dq + k0 + kc]);
        }
#pragma unroll
        for (int u = 0; u < 2; u++) {
            int idx = tid + u * 256;
            int kk = idx >> 5, sc = (idx & 31) * 4;
            cp16(smem_u32(&Bs[st * LG_B + kk * 136 + sc]), &phi[(size_t)(k0 + kk) * Sq + sc]);
        }
        cp_commit();
    };
    issue(0); issue(1);
#pragma unroll 1
    for (int c = 0; c < NC; c++) {
        cp_wait<1>();
        __syncthreads();
        if (c + 2 < NC) issue(c + 2); else cp_commit();
        mma_amk<2, 4, 20, 136, true>(&As[(c % 3) * LG_A], &Bs[(c % 3) * LG_B],
                                     mbase, nbase, acc);
    }

    // epilogue: stash logits in smem overlay + write raw logits to global
    float (*L)[132] = (float(*)[132])Sbuf;  // 64*132 = 8448 floats <= 10368
    int g = lane >> 2, tg = lane & 3;
    float* lb = g_logits + (size_t)r0 * Sq;
    __syncthreads();
#pragma unroll
    for (int i = 0; i < 2; i++)
#pragma unroll
        for (int j = 0; j < 4; j++) {
            int row = mbase + i * 16 + g, col = nbase + j * 8 + tg * 2;
            float2 lo = make_float2(acc[i][j][0], acc[i][j][1]);
            float2 hi = make_float2(acc[i][j][2], acc[i][j][3]);
            *(float2*)&L[row][col] = lo;
            *(float2*)&L[row + 8][col] = hi;
            *(float2*)&lb[(size_t)row * Sq + col] = lo;
            *(float2*)&lb[(size_t)(row + 8) * Sq + col] = hi;
        }
    __syncthreads();

    // row softmax over S=128: each warp handles 8 rows
#pragma unroll 1
    for (int q = 0; q < 8; q++) {
        int row = warp * 8 + q;
        float v[4];
        float mx = -1e30f;
#pragma unroll
        for (int j = 0; j < 4; j++) {
            v[j] = L[row][lane + j * 32];
            mx = fmaxf(mx, v[j]);
        }
#pragma unroll
        for (int off = 16; off > 0; off >>= 1)
            mx = fmaxf(mx, __shfl_xor_sync(0xffffffffu, mx, off));
        float e[4], sum = 0.f;
#pragma unroll
        for (int j = 0; j < 4; j++) {
            e[j] = expf(v[j] - mx);
            sum += e[j];
        }
#pragma unroll
        for (int off = 16; off > 0; off >>= 1)
            sum += __shfl_xor_sync(0xffffffffu, sum, off);
        float inv = 1.f / sum;
        float* cp = g_combine + (size_t)(r0 + row) * Sq;
#pragma unroll
        for (int j = 0; j < 4; j++) cp[lane + j * 32] = round_tf32(e[j] * inv);
    }
}

// ============ 2a) dispatch partials: (max, sum) over M-chunk per (b,s) =====
// grid (Sq/32, Bq, MSP), block (32, 32). 16 rows per thread, register-cached.
__global__ void dispatch_part() {
    int b = blockIdx.y, ch = blockIdx.z;
    int s = blockIdx.x * 32 + threadIdx.x;
    int tx = threadIdx.x, ty = threadIdx.y;
    const float* lp = g_logits + ((size_t)b * Mq + ch * (Mq / MSP)) * Sq + s;

    float v[16];
#pragma unroll
    for (int i = 0; i < 16; i++) v[i] = lp[(size_t)(ty + i * 32) * Sq];
    float mx = v[0];
#pragma unroll
    for (int i = 1; i < 16; i++) mx = fmaxf(mx, v[i]);
    float sum = 0.f;
#pragma unroll
    for (int i = 0; i < 16; i++) sum += expf(v[i] - mx);

    __shared__ float rm[32][33], rs[32][33];
    rm[ty][tx] = mx;
    rs[ty][tx] = sum;
    __syncthreads();
    for (int off = 16; off > 0; off >>= 1) {
        if (ty < off) {
            float m1 = rm[ty][tx], s1 = rs[ty][tx];
            float m2 = rm[ty + off][tx], s2 = rs[ty + off][tx];
            float m = fmaxf(m1, m2);
            rm[ty][tx] = m;
            rs[ty][tx] = s1 * expf(m1 - m) + s2 * expf(m2 - m);
        }
        __syncthreads();
    }
    if (ty == 0) {
        g_dmx[(ch * Bq + b) * Sq + s] = rm[0][tx];
        g_dsum[(ch * Bq + b) * Sq + s] = rs[0][tx];
    }
}

// ============ 2b) dispatch write: combine partials + normalize =============
// grid (Sq/32, Bq, MSP), block (32, 32).
__global__ void dispatch_write() {
    int b = blockIdx.y, ch = blockIdx.z;
    int s = blockIdx.x * 32 + threadIdx.x;
    int ty = threadIdx.y;

    float mx = g_dmx[(0 * Bq + b) * Sq + s];
    float sum = g_dsum[(0 * Bq + b) * Sq + s];
#pragma unroll
    for (int c = 1; c < MSP; c++) {
        float m2 = g_dmx[(c * Bq + b) * Sq + s];
        float s2 = g_dsum[(c * Bq + b) * Sq + s];
        float m = fmaxf(mx, m2);
        sum = sum * expf(mx - m) + s2 * expf(m2 - m);
        mx = m;
    }
    float inv = 1.f / sum;

    const float* lp = g_logits + ((size_t)b * Mq + ch * (Mq / MSP)) * Sq + s;
    float* dp = g_dispatch + ((size_t)b * Mq + ch * (Mq / MSP)) * Sq + s;
#pragma unroll
    for (int i = 0; i < 16; i++) {
        size_t off = (size_t)(ty + i * 32) * Sq;
        dp[off] = round_tf32(expf(lp[off] - mx) * inv);
    }
}

// ============ 3) xs partials, split-K over M ===============================
// BM=128 (ALL slots) BN=128(d), block 256 (warps 2x4, MT=4 NT=4). 3-stage.
// grid (Dq/128, 1, Bq*KV) = (8, 1, 64). NC = 2048/8/16 = 16.
__global__ void __launch_bounds__(256) xs_mma(const float* __restrict__ x) {
    const int b = blockIdx.z >> 3;
    const int kv = blockIdx.z & 7;
    const int d0 = blockIdx.x * 128;
    const int mk = kv * (Mq / KV);
    __shared__ float As[3][16 * 136];
    __shared__ float Bs[3][16 * 136];

    int tid = threadIdx.x, warp = tid >> 5, lane = tid & 31;
    int mbase = (warp >> 2) * 64, nbase = (warp & 3) * 32;
    float acc[4][4][4] = {};

    const int NC = (Mq / KV) / 16;  // 16

    auto issue = [&](int c) {
        int k0 = mk + c * 16, st = c % 3;
#pragma unroll
        for (int u = 0; u < 2; u++) {
            int idx = tid + u * 256;
            int kk = idx >> 5, sc = (idx & 31) * 4;
            cp16(smem_u32(&As[st][kk * 136 + sc]),
                 &g_dispatch[((size_t)b * Mq + k0 + kk) * Sq + sc]);
            int dc = (idx & 31) * 4;
            cp16(smem_u32(&Bs[st][kk * 136 + dc]),
                 &x[((size_t)b * Mq + k0 + kk) * Dq + d0 + dc]);
        }
        cp_commit();
    };
    issue(0); issue(1);
#pragma unroll 1
    for (int c = 0; c < NC; c++) {
        cp_wait<1>();
        __syncthreads();
        if (c + 2 < NC) issue(c + 2); else cp_commit();
        mma_akm<4, 4, 136, 136, false>(As[c % 3], Bs[c % 3], mbase, nbase, acc);
    }

    int g = lane >> 2, tg = lane & 3;
    float* pp = g_xs_part + ((size_t)kv * Bq + b) * Sq * Dq;
#pragma unroll
    for (int i = 0; i < 4; i++)
#pragma unroll
        for (int j = 0; j < 4; j++) {
            int row = mbase + i * 16 + g, col = d0 + nbase + j * 8 + tg * 2;
            *(float2*)&pp[(size_t)row * Dq + col] = make_float2(acc[i][j][0], acc[i][j][1]);
            *(float2*)&pp[(size_t)(row + 8) * Dq + col] = make_float2(acc[i][j][2], acc[i][j][3]);
        }
}

// ============ 3b) xs = sum_kv partials (tf32-rounded) ======================
__global__ void __launch_bounds__(256) xs_reduce() {
    int i = blockIdx.x * 256 + threadIdx.x;  // float4 index
    const int stride = Bq * Sq * Dq / 4;
    const float4* p = (const float4*)g_xs_part;
    float4 a = p[i];
    float sx = a.x, sy = a.y, sz = a.z, sw = a.w;
#pragma unroll
    for (int c = 1; c < KV; c++) {
        float4 v = p[i + c * stride];
        sx += v.x; sy += v.y; sz += v.z; sw += v.w;
    }
    ((float4*)g_xs)[i] = make_float4(round_tf32(sx), round_tf32(sy),
                                     round_tf32(sz), round_tf32(sw));
}

// ============ 4a) h = relu(xs @ w1 + b1)^2 per expert ======================
// BM=32 BN=128, block 128 (warps 1x4, MT=2 NT=4). 4-stage. grid (16, 32).
__global__ void __launch_bounds__(128) ffn1_mma(const float* __restrict__ w1,
                                                const float* __restrict__ b1) {
    const int n = blockIdx.y;
    const int f0 = blockIdx.x * 128;
    __shared__ float As[4][32 * 20];
    __shared__ float Bs[4][16 * 136];

    int tid = threadIdx.x, warp = tid >> 5, lane = tid & 31;
    int nbase = warp * 32;
    float acc[2][4][4] = {};

    const int NC = Dq / 16;  // 64

    auto issue = [&](int c) {
        int k0 = c * 16, st = c & 3;
        {
            int row = tid >> 2, kc = (tid & 3) * 4;
            cp16(smem_u32(&As[st][row * 20 + kc]),
                 &g_xs[(((size_t)(row >> 2)) * Sq + n * 4 + (row & 3)) * Dq + k0 + kc]);
        }
#pragma unroll
        for (int u = 0; u < 4; u++) {
            int idx = tid + u * 128;
            int kk = idx >> 5, fc = (idx & 31) * 4;
            cp16(smem_u32(&Bs[st][kk * 136 + fc]),
                 &w1[((size_t)n * Dq + k0 + kk) * Fq + f0 + fc]);
        }
        cp_commit();
    };
    issue(0); issue(1); issue(2);
#pragma unroll 1
    for (int c = 0; c < NC; c++) {
        cp_wait<2>();
        __syncthreads();
        if (c + 3 < NC) issue(c + 3); else cp_commit();
        mma_amk<2, 4, 20, 136, false>(As[c & 3], Bs[c & 3], 0, nbase, acc);
    }

    int g = lane >> 2, tg = lane & 3;
#pragma unroll
    for (int i = 0; i < 2; i++)
#pragma unroll
        for (int j = 0; j < 4; j++) {
            int row = i * 16 + g;
            int col = nbase + j * 8 + tg * 2;
#pragma unroll
            for (int half = 0; half < 2; half++) {
                int rr = row + half * 8;
                float h0 = acc[i][j][half * 2 + 0] + b1[(size_t)n * Fq + f0 + col];
                float h1 = acc[i][j][half * 2 + 1] + b1[(size_t)n * Fq + f0 + col + 1];
                h0 = fmaxf(h0, 0.f); h1 = fmaxf(h1, 0.f);
                float* hp = &g_h[(((size_t)(rr >> 2)) * Sq + n * 4 + (rr & 3)) * Fq + f0 + col];
                *(float2*)hp = make_float2(round_tf32(h0 * h0), round_tf32(h1 * h1));
            }
        }
}

// ============ 4b) y = h @ w2 + b2 per expert ===============================
// BM=32 BN=128, block 128 (warps 1x4, MT=2 NT=4). 4-stage. grid (8, 32).
__global__ void __launch_bounds__(128) ffn2_mma(const float* __restrict__ w2,
                                                const float* __restrict__ b2) {
    const int n = blockIdx.y;
    const int d0 = blockIdx.x * 128;
    __shared__ float As[4][32 * 20];
    __shared__ float Bs[4][16 * 136];

    int tid = threadIdx.x, warp = tid >> 5, lane = tid & 31;
    int nbase = warp * 32;
    float acc[2][4][4] = {};

    const int NC = Fq / 16;  // 128

    auto issue = [&](int c) {
        int k0 = c * 16, st = c & 3;
        {
            int row = tid >> 2, kc = (tid & 3) * 4;
            cp16(smem_u32(&As[st][row * 20 + kc]),
                 &g_h[(((size_t)(row >> 2)) * Sq + n * 4 + (row & 3)) * Fq + k0 + kc]);
        }
#pragma unroll
        for (int u = 0; u < 4; u++) {
            int idx = tid + u * 128;
            int kk = idx >> 5, dc = (idx & 31) * 4;
            cp16(smem_u32(&Bs[st][kk * 136 + dc]),
                 &w2[((size_t)n * Fq + k0 + kk) * Dq + d0 + dc]);
        }
        cp_commit();
    };
    issue(0); issue(1); issue(2);
#pragma unroll 1
    for (int c = 0; c < NC; c++) {
        cp_wait<2>();
        __syncthreads();
        if (c + 3 < NC) issue(c + 3); else cp_commit();
        mma_amk<2, 4, 20, 136, false>(As[c & 3], Bs[c & 3], 0, nbase, acc);
    }

    int g = lane >> 2, tg = lane & 3;
#pragma unroll
    for (int i = 0; i < 2; i++)
#pragma unroll
        for (int j = 0; j < 4; j++) {
            int row = i * 16 + g;
            int col = nbase + j * 8 + tg * 2;
#pragma unroll
            for (int half = 0; half < 2; half++) {
                int rr = row + half * 8;
                float y0 = acc[i][j][half * 2 + 0] + b2[(size_t)n * Dq + d0 + col];
                float y1 = acc[i][j][half * 2 + 1] + b2[(size_t)n * Dq + d0 + col + 1];
                float* yp = &g_y[(((size_t)(rr >> 2)) * Sq + n * 4 + (rr & 3)) * Dq + d0 + col];
                *(float2*)yp = make_float2(y0, y1);
            }
        }
}

// ============ 5) out[b,m,d] = sum_s combine[b,m,s] * y[b,s,d] ==============
// BM=128(m) BN=128(d), block 256 (warps 2x4, MT=4 NT=4). 3-stage, single sync.
// grid (8, 16, 8). K=S=128.
__global__ void __launch_bounds__(256) out_mma(float* __restrict__ out) {
    const int b = blockIdx.z;
    const int m0 = blockIdx.y * 128;
    const int d0 = blockIdx.x * 128;
    __shared__ float As[3][128 * 20];
    __shared__ float Bs[3][16 * 136];

    int tid = threadIdx.x, warp = tid >> 5, lane = tid & 31;
    int mbase = (warp >> 2) * 64, nbase = (warp & 3) * 32;
    float acc[4][4][4] = {};

    const float* cb = g_combine + ((size_t)b * Mq + m0) * Sq;
    const int NC = Sq / 16;  // 8

    auto issue = [&](int c) {
        int k0 = c * 16, st = c % 3;
#pragma unroll
        for (int u = 0; u < 2; u++) {
            int idx = tid + u * 256;
            int row = idx >> 2, kc = (idx & 3) * 4;
            cp16(smem_u32(&As[st][row * 20 + kc]), &cb[(size_t)row * Sq + k0 + kc]);
            int kk = idx >> 5, dc = (idx & 31) * 4;
            cp16(smem_u32(&Bs[st][kk * 136 + dc]),
                 &g_y[((size_t)b * Sq + k0 + kk) * Dq + d0 + dc]);
        }
        cp_commit();
    };
    issue(0); issue(1);
#pragma unroll 1
    for (int c = 0; c < NC; c++) {
        cp_wait<1>();
        __syncthreads();
        if (c + 2 < NC) issue(c + 2); else cp_commit();
        mma_amk<4, 4, 20, 136, false>(As[c % 3], Bs[c % 3], mbase, nbase, acc);
    }

    int g = lane >> 2, tg = lane & 3;
    float* ob = out + ((size_t)b * Mq + m0) * Dq + d0;
#pragma unroll
    for (int i = 0; i < 4; i++)
#pragma unroll
        for (int j = 0; j < 4; j++) {
            int row = mbase + i * 16 + g, col = nbase + j * 8 + tg * 2;
            *(float2*)&ob[(size_t)row * Dq + col] = make_float2(acc[i][j][0], acc[i][j][1]);
            *(float2*)&ob[(size_t)(row + 8) * Dq + col] = make_float2(acc[i][j][2], acc[i][j][3]);
        }
}

// ---------------------------------------------------------------------------
extern "C" void kernel_launch(void* const* d_in, const int* in_sizes, int n_in,
                              void* d_out, int out_size) {
    const float* x   = (const float*)d_in[0];
    const float* phi = (const float*)d_in[1];
    const float* w1  = (const float*)d_in[2];
    const float* b1  = (const float*)d_in[3];
    const float* w2  = (const float*)d_in[4];
    const float* b2  = (const float*)d_in[5];
    float* out = (float*)d_out;

    logits_mma<<<(Bq * Mq) / 64, 256>>>(x, phi);
    dispatch_part<<<dim3(Sq / 32, Bq, MSP), dim3(32, 32)>>>();
    dispatch_write<<<dim3(Sq / 32, Bq, MSP), dim3(32, 32)>>>();
    xs_mma<<<dim3(Dq / 128, 1, Bq * KV), 256>>>(x);
    xs_reduce<<<(Bq * Sq * Dq / 4) / 256, 256>>>();
    ffn1_mma<<<dim3(Fq / 128, Nq), 128>>>(w1, b1);
    ffn2_mma<<<dim3(Dq / 128, Nq), 128>>>(w2, b2);
    out_mma<<<dim3(Dq / 128, Mq / 128, Bq), 256>>>(out);
}